// round 14
// baseline (speedup 1.0000x reference)
#include <cuda_runtime.h>
#include <cuda_bf16.h>
#include <math.h>
#include <stdint.h>

#define BB 2
#define LL 2048
#define KK 32
#define HH 128
#define PP 8
#define MSG 456
#define LDT 40        /* tf32 FFN tiles */
#define NB (BB*LL)    /* 4096 nodes */

#define LDK 344       /* bf16 elems per mi row (688B stride, conflict-free) */
#define LDH 136       /* bf16 elems per h row (272B stride) */
#define LDF 132       /* fp32 msg row */
#define H1_OFF 0      /* bf16 offset of h1 in A0 */
#define H2_OFF 4352   /* bf16 offset of h2 in A0 (byte 8704) */

// -------- scratch --------
__device__ float g_R [NB*9];
__device__ float g_t [NB*3];
__device__ float g_pl[NB*24];
__device__ float g_pg[NB*24];
__device__ float g_hV[NB*HH];
__device__ float g_xn[NB*HH];
__device__ float g_u [NB*HH];
__device__ float g_ff[(size_t)NB*4*HH];

// tf32 packed weights
__device__ float g_Wdinp [16*64*64];
__device__ float g_Wdoutp[64*16*64];
__device__ float g_W1hp  [16*16*64];
__device__ float g_W11hp [16*16*64];

// bf16 packed message weights, nq-grouped:
// element (kc, tile j=g*4+jl, lane, reg r) at [((kc*4+g)*32+lane)*8 + jl*2 + r]
// per-kc stride = 1024 uint32 (same as old layout).
__device__ uint32_t g_W1pb [29*16*64];
__device__ uint32_t g_W2pb [ 8*16*64];
__device__ uint32_t g_W3pb [ 8*16*64];
__device__ uint32_t g_W11pb[29*16*64];
__device__ uint32_t g_W12pb[ 8*16*64];
__device__ uint32_t g_W13pb[ 8*16*64];

__device__ __forceinline__ float gelu_f(float x){
    return 0.5f*x*(1.0f+erff(x*0.70710678118654752440f));
}
__device__ __forceinline__ float tf32r(float x){
    uint32_t u; asm("cvt.rna.tf32.f32 %0, %1;" : "=r"(u) : "f"(x));
    return __uint_as_float(u);
}
__device__ __forceinline__ uint32_t bf16x2(float lo, float hi){
    __nv_bfloat162 h = __floats2bfloat162_rn(lo, hi);
    return *reinterpret_cast<uint32_t*>(&h);
}
__device__ __forceinline__ void mma8(float* c, const uint32_t* a, uint32_t b0, uint32_t b1){
    asm volatile("mma.sync.aligned.m16n8k8.row.col.f32.tf32.tf32.f32 "
        "{%0,%1,%2,%3},{%4,%5,%6,%7},{%8,%9},{%0,%1,%2,%3};"
        : "+f"(c[0]),"+f"(c[1]),"+f"(c[2]),"+f"(c[3])
        : "r"(a[0]),"r"(a[1]),"r"(a[2]),"r"(a[3]),"r"(b0),"r"(b1));
}
__device__ __forceinline__ void mma16816(float* c, const uint32_t* a, uint32_t b0, uint32_t b1){
    asm volatile("mma.sync.aligned.m16n8k16.row.col.f32.bf16.bf16.f32 "
        "{%0,%1,%2,%3},{%4,%5,%6,%7},{%8,%9},{%0,%1,%2,%3};"
        : "+f"(c[0]),"+f"(c[1]),"+f"(c[2]),"+f"(c[3])
        : "r"(a[0]),"r"(a[1]),"r"(a[2]),"r"(a[3]),"r"(b0),"r"(b1));
}
__device__ __forceinline__ void ldsm4(uint32_t* r, uint32_t addr){
    asm volatile("ldmatrix.sync.aligned.m8n8.x4.shared.b16 {%0,%1,%2,%3}, [%4];"
        : "=r"(r[0]),"=r"(r[1]),"=r"(r[2]),"=r"(r[3]) : "r"(addr));
}

// ============================================================
// tf32 weight packs merged: z=0 Wdin, z=1 Wdout, z=2 W1 head, z=3 W11 head
// ============================================================
__global__ void k_packA(const float* __restrict__ Wdin, const float* __restrict__ Wdout,
                        const float* __restrict__ W1,  const float* __restrict__ W11,
                        float* pdin, float* pdout, float* pw1h, float* pw11h)
{
    int z = blockIdx.z;
    const float* W; float* out; int N, KC;
    switch(z){
        case 0: W=Wdin;  out=pdin;  N=512; KC=16; break;
        case 1: W=Wdout; out=pdout; N=128; KC=64; break;
        case 2: W=W1;    out=pw1h;  N=128; KC=16; break;
        default:W=W11;   out=pw11h; N=128; KC=16; break;
    }
    int ntiles = N >> 3;
    int kc = blockIdx.x; if (kc >= KC) return;
    int j  = blockIdx.y*16 + threadIdx.y; if (j >= ntiles) return;
    int lane = threadIdx.x;
    int row  = kc*8 + (lane&3);
    int col  = j*8 + (lane>>2);
    float b0 = W[(size_t)row*N + col];
    float b1 = W[(size_t)(row+4)*N + col];
    float* o = out + (((size_t)kc*ntiles + j)*32 + lane)*2;
    o[0] = tf32r(b0); o[1] = tf32r(b1);
}

// ============================================================
// bf16 weight pack (nq-grouped layout). grid(29,16,6) block 32.
// ============================================================
__global__ void k_packb(const float* __restrict__ W1,const float* __restrict__ W2,
                        const float* __restrict__ W3,const float* __restrict__ W11,
                        const float* __restrict__ W12,const float* __restrict__ W13,
                        uint32_t* o1,uint32_t* o2,uint32_t* o3,
                        uint32_t* o11,uint32_t* o12,uint32_t* o13)
{
    int z = blockIdx.z;
    const float* src; uint32_t* dst; int Ktot;
    switch(z){
        case 0: src=W1;  dst=o1;  Ktot=MSG; break;
        case 1: src=W2;  dst=o2;  Ktot=HH;  break;
        case 2: src=W3;  dst=o3;  Ktot=HH;  break;
        case 3: src=W11; dst=o11; Ktot=MSG; break;
        case 4: src=W12; dst=o12; Ktot=HH;  break;
        default:src=W13; dst=o13; Ktot=HH;  break;
    }
    int kc = blockIdx.x;
    if (kc >= (Ktot+15)/16) return;
    int j = blockIdx.y, lane = threadIdx.x;
    int g = j>>2, jl = j&3;
    int n = j*8 + (lane>>2);
    #pragma unroll
    for (int r=0;r<2;r++){
        int k = kc*16 + (lane&3)*2 + 8*r;
        float v0 = (k   < Ktot)? src[(size_t)k*HH + n]     : 0.f;
        float v1 = (k+1 < Ktot)? src[(size_t)(k+1)*HH + n] : 0.f;
        dst[(((size_t)kc*4 + g)*32 + lane)*8 + jl*2 + r] = bf16x2(v0, v1);
    }
}

// ============================================================
// tf32 MMA core (NJ n-tiles per warp)
// ============================================================
template<int NKC, int NJ>
__device__ __forceinline__ void mma_core(const float* __restrict__ Bpack, int ntiles, int jbase,
                                         const float* sA, float c[2][NJ][4], int lane)
{
    int qid = lane>>2, tig = lane&3;
    #pragma unroll
    for (int mt=0;mt<2;mt++)
        #pragma unroll
        for (int j=0;j<NJ;j++)
            #pragma unroll
            for (int i=0;i<4;i++) c[mt][j][i]=0.f;
    const float* bbase = Bpack + (size_t)jbase*64 + lane*2;
    #pragma unroll 4
    for (int kc=0; kc<NKC; kc++){
        const float* a0p = sA + (kc*8+tig)*LDT;
        const float* a1p = a0p + 4*LDT;
        uint32_t a[2][4];
        a[0][0]=__float_as_uint(a0p[qid]);
        a[0][1]=__float_as_uint(a0p[qid+8]);
        a[0][2]=__float_as_uint(a1p[qid]);
        a[0][3]=__float_as_uint(a1p[qid+8]);
        a[1][0]=__float_as_uint(a0p[qid+16]);
        a[1][1]=__float_as_uint(a0p[qid+24]);
        a[1][2]=__float_as_uint(a1p[qid+16]);
        a[1][3]=__float_as_uint(a1p[qid+24]);
        const float* bp = bbase + (size_t)kc*ntiles*64;
        #pragma unroll
        for (int j=0;j<NJ;j++){
            float2 bv = *reinterpret_cast<const float2*>(bp + (size_t)j*64);
            uint32_t b0=__float_as_uint(bv.x), b1=__float_as_uint(bv.y);
            mma8(c[0][j], a[0], b0, b1);
            mma8(c[1][j], a[1], b0, b1);
        }
    }
}

// ============================================================
// Fused per-pass prep: frames (or R reload) + head GEMM -> g_u
// + 24-dim projection -> g_pl + p_global -> g_pg.
// ============================================================
struct PrepSmem {
    float sA[HH*LDT];
    float sW[HH*24];
    float spl[32*24];
    float sR[32*9];
    float st[32*3];
};

__global__ void k_prep(const float* __restrict__ src,
                       const float* __restrict__ Wp,
                       const float* __restrict__ bp,
                       const float* __restrict__ Bpack,
                       const float* __restrict__ biasHead,
                       const float* __restrict__ X,
                       int do_frames)
{
    __shared__ PrepSmem S;
    int rb = blockIdx.x;
    int t = threadIdx.x;
    int lane=t&31, warp=t>>5;

    {
        int m = t>>2; int k0 = (t&3)*32;
        const float* s = src + ((size_t)(rb*32+m))*HH + k0;
        #pragma unroll
        for (int i=0;i<8;i++){
            float4 v = *reinterpret_cast<const float4*>(s + i*4);
            S.sA[(k0+i*4+0)*LDT+m]=tf32r(v.x);
            S.sA[(k0+i*4+1)*LDT+m]=tf32r(v.y);
            S.sA[(k0+i*4+2)*LDT+m]=tf32r(v.z);
            S.sA[(k0+i*4+3)*LDT+m]=tf32r(v.w);
        }
    }
    for (int i=t;i<HH*24;i+=128) S.sW[i] = Wp[i];
    if (do_frames){
        if (t < 32){
            int node = rb*32 + t;
            const float* Xp = X + (size_t)node*12;
            float Nx=Xp[0],Ny=Xp[1],Nz=Xp[2];
            float Ax=Xp[3],Ay=Xp[4],Az=Xp[5];
            float Cx=Xp[6],Cy=Xp[7],Cz=Xp[8];
            float e0x=Ax-Nx, e0y=Ay-Ny, e0z=Az-Nz;
            float inv = 1.0f/sqrtf(e0x*e0x+e0y*e0y+e0z*e0z + 1e-8f);
            e0x*=inv; e0y*=inv; e0z*=inv;
            float e1x=Cx-Ax, e1y=Cy-Ay, e1z=Cz-Az;
            float d = e0x*e1x+e0y*e1y+e0z*e1z;
            e1x-=e0x*d; e1y-=e0y*d; e1z-=e0z*d;
            inv = 1.0f/sqrtf(e1x*e1x+e1y*e1y+e1z*e1z + 1e-8f);
            e1x*=inv; e1y*=inv; e1z*=inv;
            float e2x=e0y*e1z-e0z*e1y;
            float e2y=e0z*e1x-e0x*e1z;
            float e2z=e0x*e1y-e0y*e1x;
            float R0=e0x,R1=e1x,R2=e2x,R3=e0y,R4=e1y,R5=e2y,R6=e0z,R7=e1z,R8=e2z;
            S.sR[t*9+0]=R0; S.sR[t*9+1]=R1; S.sR[t*9+2]=R2;
            S.sR[t*9+3]=R3; S.sR[t*9+4]=R4; S.sR[t*9+5]=R5;
            S.sR[t*9+6]=R6; S.sR[t*9+7]=R7; S.sR[t*9+8]=R8;
            S.st[t*3+0]=Ax; S.st[t*3+1]=Ay; S.st[t*3+2]=Az;
            float* Rg = g_R + node*9;
            Rg[0]=R0; Rg[1]=R1; Rg[2]=R2; Rg[3]=R3; Rg[4]=R4;
            Rg[5]=R5; Rg[6]=R6; Rg[7]=R7; Rg[8]=R8;
            g_t[node*3+0]=Ax; g_t[node*3+1]=Ay; g_t[node*3+2]=Az;
        }
    } else {
        for (int i=t;i<32*9;i+=128) S.sR[i] = g_R[(size_t)rb*32*9 + i];
        for (int i=t;i<32*3;i+=128) S.st[i] = g_t[(size_t)rb*32*3 + i];
    }
    __syncthreads();

    {
        float c[2][4][4];
        mma_core<16,4>(Bpack, 16, warp*4, S.sA, c, lane);
        int qid=lane>>2, tig=lane&3;
        #pragma unroll
        for (int j=0;j<4;j++){
            int n = (warp*4+j)*8 + tig*2;
            float b0=biasHead[n], b1=biasHead[n+1];
            #pragma unroll
            for (int mt=0;mt<2;mt++){
                int r = rb*32 + mt*16 + qid;
                g_u[(size_t)r*HH + n]       = c[mt][j][0]+b0;
                g_u[(size_t)r*HH + n+1]     = c[mt][j][1]+b1;
                g_u[(size_t)(r+8)*HH + n]   = c[mt][j][2]+b0;
                g_u[(size_t)(r+8)*HH + n+1] = c[mt][j][3]+b1;
            }
        }
    }

    #pragma unroll
    for (int i=0;i<6;i++){
        int idx = i*128 + t;
        int m = idx/24, j = idx%24;
        float acc = bp[j];
        #pragma unroll 8
        for (int f=0; f<HH; f++) acc += S.sA[f*LDT+m]*S.sW[f*24+j];
        S.spl[m*24+j] = acc;
        g_pl[((size_t)rb*32+m)*24 + j] = acc;
    }
    __syncthreads();

    #pragma unroll
    for (int i=0;i<6;i++){
        int idx = i*128 + t;
        int m = idx/24, l = idx%24;
        int p = l/3, ii = l%3;
        const float* R = S.sR + m*9;
        const float* pl = S.spl + m*24 + p*3;
        g_pg[((size_t)rb*32+m)*24 + l] =
            S.st[m*3+ii] + R[ii*3+0]*pl[0] + R[ii*3+1]*pl[1] + R[ii*3+2]*pl[2];
    }
}

// ============================================================
// Message-kernel shared memory: ONE node per CTA, A1 eliminated (~23.6KB)
// ============================================================
struct __align__(16) MsgSmem1 {
    __nv_bfloat16 A0[KK*LDK];   // 22016 B
    float hv[HH];
    float uu[HH];
    float Rr[9], tvv[3], pll[24], pgg[24];
    float mask[KK];
    int   nbidx[KK];
    float red[8];
};

// ============================================================
// bf16 MMA core, nq-grouped B: 2 x ld.v4 per kc (was 4 x ld.v2).
// ============================================================
template<int NKC>
__device__ __forceinline__ void mma_bf16(const uint32_t* __restrict__ Bp, int nq,
                                         uint32_t aAddr, int ldkB, int lane,
                                         float c[2][4][4])
{
    #pragma unroll
    for (int mt=0;mt<2;mt++)
        #pragma unroll
        for (int j=0;j<4;j++)
            #pragma unroll
            for (int i=0;i<4;i++) c[mt][j][i]=0.f;

    uint32_t arow = aAddr + (uint32_t)((lane&15)*ldkB) + ((lane>>4)&1)*16;
    const uint4* bbase = reinterpret_cast<const uint4*>(Bp + ((size_t)nq*32 + lane)*8);
    #pragma unroll
    for (int kc=0; kc<NKC; kc++){
        uint32_t a[2][4];
        #pragma unroll
        for (int mt=0;mt<2;mt++) ldsm4(a[mt], arow + mt*16*ldkB + kc*32);
        const uint4* bp = bbase + (size_t)kc*256;   // per-kc stride 1024 uint32 = 256 uint4
        uint4 lo = bp[0];
        uint4 hi = bp[1];
        #pragma unroll
        for (int mt=0;mt<2;mt++){
            mma16816(c[mt][0], a[mt], lo.x, lo.y);
            mma16816(c[mt][1], a[mt], lo.z, lo.w);
            mma16816(c[mt][2], a[mt], hi.x, hi.y);
            mma16816(c[mt][3], a[mt], hi.z, hi.w);
        }
    }
}

// epilogues: rows are local [0,32)
__device__ __forceinline__ void epi_gelu_u(float c[2][4][4], const float* __restrict__ uv,
                                           __nv_bfloat16* dst, int lane, int nq)
{
    int qid=lane>>2, tig=lane&3;
    #pragma unroll
    for (int mt=0;mt<2;mt++){
        int r0 = mt*16 + qid;
        #pragma unroll
        for (int j=0;j<4;j++){
            int n0 = nq*32 + j*8 + tig*2;
            float b0=uv[n0], b1=uv[n0+1];
            *reinterpret_cast<uint32_t*>(dst + (size_t)r0*LDH + n0) =
                bf16x2(gelu_f(c[mt][j][0]+b0), gelu_f(c[mt][j][1]+b1));
            *reinterpret_cast<uint32_t*>(dst + (size_t)(r0+8)*LDH + n0) =
                bf16x2(gelu_f(c[mt][j][2]+b0), gelu_f(c[mt][j][3]+b1));
        }
    }
}

__device__ __forceinline__ void epi_gelu_bf16(float c[2][4][4], const float* __restrict__ bias,
                                              __nv_bfloat16* dst, int lane, int nq)
{
    int qid=lane>>2, tig=lane&3;
    #pragma unroll
    for (int mt=0;mt<2;mt++){
        int r0 = mt*16 + qid;
        #pragma unroll
        for (int j=0;j<4;j++){
            int n0 = nq*32 + j*8 + tig*2;
            float b0=bias[n0], b1=bias[n0+1];
            *reinterpret_cast<uint32_t*>(dst + (size_t)r0*LDH + n0) =
                bf16x2(gelu_f(c[mt][j][0]+b0), gelu_f(c[mt][j][1]+b1));
            *reinterpret_cast<uint32_t*>(dst + (size_t)(r0+8)*LDH + n0) =
                bf16x2(gelu_f(c[mt][j][2]+b0), gelu_f(c[mt][j][3]+b1));
        }
    }
}

__device__ __forceinline__ void epi_float(float c[2][4][4], const float* __restrict__ bias,
                                          float* msgF, int lane, int nq)
{
    int qid=lane>>2, tig=lane&3;
    #pragma unroll
    for (int mt=0;mt<2;mt++){
        int r0 = mt*16 + qid;
        #pragma unroll
        for (int j=0;j<4;j++){
            int n0 = nq*32 + j*8 + tig*2;
            float b0=bias[n0], b1=bias[n0+1];
            msgF[(size_t)r0*LDF + n0]       = c[mt][j][0]+b0;
            msgF[(size_t)r0*LDF + n0+1]     = c[mt][j][1]+b1;
            msgF[(size_t)(r0+8)*LDF + n0]   = c[mt][j][2]+b0;
            msgF[(size_t)(r0+8)*LDF + n0+1] = c[mt][j][3]+b1;
        }
    }
}

// Param load. t in [0,128).
__device__ __forceinline__ void load_node_params(MsgSmem1& S, int node, int t,
                                                 const float* __restrict__ hVsrc,
                                                 const int* __restrict__ Eidx,
                                                 const float* __restrict__ maskA)
{
    S.hv[t] = hVsrc[(size_t)node*HH + t];
    S.uu[t] = g_u[(size_t)node*HH + t];
    if (t < KK){
        S.nbidx[t] = Eidx[(size_t)node*KK + t];
        S.mask[t]  = maskA ? maskA[(size_t)node*KK + t] : 1.0f;
    }
    if (t < 9)  S.Rr[t]  = g_R[node*9 + t];
    if (t < 3)  S.tvv[t] = g_t[node*3 + t];
    if (t < 24){ S.pll[t] = g_pl[node*24 + t]; S.pgg[t] = g_pg[node*24 + t]; }
}

// mi build: warp w builds rows w*8..+8; geometry all 128 threads, 2 points each.
__device__ __forceinline__ void build_mi1(MsgSmem1& S, int node, int b, int w,
                                          int lane, int t,
                                          const float* __restrict__ hVsrc,
                                          const float* __restrict__ hE)
{
    #pragma unroll
    for (int i=0;i<8;i++){
        int gr = w*8 + i;
        size_t e = (size_t)node*KK + gr;
        int nb = S.nbidx[gr];
        const float4* he4 = reinterpret_cast<const float4*>(hE + e*HH);
        const float4* nb4 = reinterpret_cast<const float4*>(hVsrc + ((size_t)b*LL + nb)*HH);
        __nv_bfloat16* row = S.A0 + (size_t)gr*LDK;
        float4 x;
        x = he4[lane];
        *reinterpret_cast<uint2*>(row + lane*4)      = make_uint2(bf16x2(x.x,x.y), bf16x2(x.z,x.w));
        x = nb4[lane];
        *reinterpret_cast<uint2*>(row + HH + lane*4) = make_uint2(bf16x2(x.x,x.y), bf16x2(x.z,x.w));
        if (lane < 8) reinterpret_cast<uint32_t*>(row + 328)[lane] = 0u;  // pad 328..343
    }
    {
        int gr = t>>2;
        int p0 = (t&3)*2;
        int nb = S.nbidx[gr];
        const float* npg = g_pg + ((size_t)b*LL + nb)*24;
        __nv_bfloat16* q = S.A0 + (size_t)gr*LDK + 2*HH;
        #pragma unroll
        for (int p=p0;p<p0+2;p++){
            float plx=S.pll[p*3], ply=S.pll[p*3+1], plz=S.pll[p*3+2];
            q[p*3+0]=__float2bfloat16_rn(plx);
            q[p*3+1]=__float2bfloat16_rn(ply);
            q[p*3+2]=__float2bfloat16_rn(plz);
            q[24+p] =__float2bfloat16_rn(sqrtf(plx*plx+ply*ply+plz*plz+1e-8f));
            float dx=npg[p*3+0]-S.tvv[0], dy=npg[p*3+1]-S.tvv[1], dz=npg[p*3+2]-S.tvv[2];
            float nlx = S.Rr[0]*dx + S.Rr[3]*dy + S.Rr[6]*dz;
            float nly = S.Rr[1]*dx + S.Rr[4]*dy + S.Rr[7]*dz;
            float nlz = S.Rr[2]*dx + S.Rr[5]*dy + S.Rr[8]*dz;
            q[32+p*3+0]=__float2bfloat16_rn(nlx);
            q[32+p*3+1]=__float2bfloat16_rn(nly);
            q[32+p*3+2]=__float2bfloat16_rn(nlz);
            q[56+p]=__float2bfloat16_rn(sqrtf(nlx*nlx+nly*nly+nlz*nlz+1e-8f));
            float gx=S.pgg[p*3+0]-npg[p*3+0];
            float gy=S.pgg[p*3+1]-npg[p*3+1];
            float gz=S.pgg[p*3+2]-npg[p*3+2];
            q[64+p]=__float2bfloat16_rn(sqrtf(gx*gx+gy*gy+gz*gz+1e-8f));
        }
    }
}

// Three chained GEMMs, A1-free region reuse inside A0.
__device__ __forceinline__ void run_msg_gemms(MsgSmem1& S,
    const uint32_t* __restrict__ B1,
    const uint32_t* __restrict__ B2, const float* __restrict__ b2,
    const uint32_t* __restrict__ B3, const float* __restrict__ b3,
    int w, int lane)
{
    uint32_t a0 = (uint32_t)__cvta_generic_to_shared(S.A0);
    float* msgF = reinterpret_cast<float*>(S.A0);
    float c[2][4][4];

    // GEMM1 reads mi (full A0). Skip offset 8*1024 uint32 (kc 0..7 handled via g_u).
    mma_bf16<21>(B1 + (size_t)8*16*64, w, a0, LDK*2, lane, c);
    __syncthreads();                              // all mi reads done
    epi_gelu_u(c, S.uu, S.A0 + H1_OFF, lane, w);  // h1 -> [0,8704)
    __syncthreads();                              // h1 ready

    // GEMM2 reads h1, writes h2 -> [8704,17408)
    mma_bf16<8>(B2, w, a0 + H1_OFF*2, LDH*2, lane, c);
    epi_gelu_bf16(c, b2, S.A0 + H2_OFF, lane, w);
    __syncthreads();                              // h2 ready

    // GEMM3 reads h2, writes msgF fp32 -> [0,16896) after barrier
    mma_bf16<8>(B3, w, a0 + H2_OFF*2, LDH*2, lane, c);
    __syncthreads();                              // all h2 reads done
    epi_float(c, b3, msgF, lane, w);
    __syncthreads();
}

// ============================================================
// Node message kernel: 1 node/CTA, 128 threads, 8 CTAs/SM
// ============================================================
__global__ __launch_bounds__(128,8) void k_node(
    const float* __restrict__ hV, const float* __restrict__ hE,
    const int* __restrict__ Eidx, const float* __restrict__ maskA,
    const float* __restrict__ b2, const float* __restrict__ b3,
    const float* __restrict__ g1, const float* __restrict__ be1)
{
    extern __shared__ char smem_raw[];
    MsgSmem1& S = *reinterpret_cast<MsgSmem1*>(smem_raw);
    int node = blockIdx.x;
    int b    = node / LL;
    int t    = threadIdx.x;
    int w = t>>5, lane = t&31;

    load_node_params(S, node, t, hV, Eidx, maskA);
    __syncthreads();
    build_mi1(S, node, b, w, lane, t, hV, hE);
    __syncthreads();
    run_msg_gemms(S, g_W1pb, g_W2pb, b2, g_W3pb, b3, w, lane);

    const float* msgF = reinterpret_cast<const float*>(S.A0);
    float acc = 0.f;
    #pragma unroll
    for (int r=0;r<KK;r++) acc += S.mask[r] * msgF[(size_t)r*LDF + t];
    float x = S.hv[t] + acc*(1.0f/KK);
    float s=x, q=x*x;
    #pragma unroll
    for (int o=16;o>0;o>>=1){
        s += __shfl_down_sync(0xffffffffu, s, o);
        q += __shfl_down_sync(0xffffffffu, q, o);
    }
    if (lane==0){ S.red[w]=s; S.red[4+w]=q; }
    __syncthreads();
    float ts = S.red[0]+S.red[1]+S.red[2]+S.red[3];
    float tq = S.red[4]+S.red[5]+S.red[6]+S.red[7];
    float mu = ts*(1.0f/HH);
    float rstd = rsqrtf(tq*(1.0f/HH)-mu*mu+1e-5f);
    g_xn[(size_t)node*HH + t] = (x-mu)*rstd*g1[t] + be1[t];
}

// ============================================================
// Edge message kernel: 1 node/CTA
// ============================================================
__global__ __launch_bounds__(128,8) void k_edge(
    const float* __restrict__ hE, const int* __restrict__ Eidx,
    const float* __restrict__ b2, const float* __restrict__ b3,
    const float* __restrict__ g3, const float* __restrict__ be3,
    float* __restrict__ out_hE)
{
    extern __shared__ char smem_raw[];
    MsgSmem1& S = *reinterpret_cast<MsgSmem1*>(smem_raw);
    int node = blockIdx.x;
    int b    = node / LL;
    int t    = threadIdx.x;
    int w = t>>5, lane = t&31;

    load_node_params(S, node, t, g_hV, Eidx, (const float*)0);
    __syncthreads();
    build_mi1(S, node, b, w, lane, t, g_hV, hE);
    __syncthreads();
    run_msg_gemms(S, g_W11pb, g_W12pb, b2, g_W13pb, b3, w, lane);

    const float* msgF = reinterpret_cast<const float*>(S.A0);
    #pragma unroll
    for (int i=0;i<8;i++){
        int grl = w*8+i;
        size_t e = (size_t)node*KK + grl;
        float4 hv_ = reinterpret_cast<const float4*>(hE + e*HH)[lane];
        float4 mv  = reinterpret_cast<const float4*>(msgF + (size_t)grl*LDF)[lane];
        float x0 = mv.x+hv_.x, x1 = mv.y+hv_.y, x2 = mv.z+hv_.z, x3 = mv.w+hv_.w;
        float s = x0+x1+x2+x3;
        float q = x0*x0+x1*x1+x2*x2+x3*x3;
        #pragma unroll
        for (int o=16;o>0;o>>=1){
            s += __shfl_xor_sync(0xffffffffu, s, o);
            q += __shfl_xor_sync(0xffffffffu, q, o);
        }
        float mu = s*(1.0f/HH);
        float rstd = rsqrtf(q*(1.0f/HH)-mu*mu+1e-5f);
        int f0 = lane*4;
        float4 gg = *reinterpret_cast<const float4*>(g3 + f0);
        float4 bb = *reinterpret_cast<const float4*>(be3 + f0);
        float4 o4;
        o4.x = (x0-mu)*rstd*gg.x + bb.x;
        o4.y = (x1-mu)*rstd*gg.y + bb.y;
        o4.z = (x2-mu)*rstd*gg.z + bb.z;
        o4.w = (x3-mu)*rstd*gg.w + bb.w;
        *reinterpret_cast<float4*>(out_hE + e*HH + f0) = o4;
    }
}

// ============================================================
// tf32 FFN (unchanged)
// ============================================================
__global__ void k_ffn1(const float* __restrict__ bdin)
{
    __shared__ float sA[HH*LDT];
    int rb = blockIdx.x, cb = blockIdx.y;
    int t = threadIdx.x;
    int lane=t&31, warp=t>>5;

    int m = t>>2; int k0 = (t&3)*32;
    const float* src = g_xn + ((size_t)(rb*32+m))*HH + k0;
    #pragma unroll
    for (int i=0;i<8;i++){
        float4 v = *reinterpret_cast<const float4*>(src + i*4);
        sA[(k0+i*4+0)*LDT+m]=tf32r(v.x);
        sA[(k0+i*4+1)*LDT+m]=tf32r(v.y);
        sA[(k0+i*4+2)*LDT+m]=tf32r(v.z);
        sA[(k0+i*4+3)*LDT+m]=tf32r(v.w);
    }
    __syncthreads();

    float c[2][4][4];
    mma_core<16,4>(g_Wdinp, 64, cb*16 + warp*4, sA, c, lane);

    int qid=lane>>2, tig=lane&3;
    #pragma unroll
    for (int j=0;j<4;j++){
        int n = (cb*16+warp*4+j)*8 + tig*2;
        float b0=bdin[n], b1=bdin[n+1];
        #pragma unroll
        for (int mt=0;mt<2;mt++){
            int r = rb*32 + mt*16 + qid;
            g_ff[(size_t)r*512 + n]       = gelu_f(c[mt][j][0]+b0);
            g_ff[(size_t)r*512 + n+1]     = gelu_f(c[mt][j][1]+b1);
            g_ff[(size_t)(r+8)*512 + n]   = gelu_f(c[mt][j][2]+b0);
            g_ff[(size_t)(r+8)*512 + n+1] = gelu_f(c[mt][j][3]+b1);
        }
    }
}

struct FfnSmem {
    float sA[4*HH*LDT];
    float mu[32], rstd[32];
};

__global__ void k_ffn2(const float* __restrict__ bdout,
                       const float* __restrict__ g2, const float* __restrict__ be2,
                       const float* __restrict__ maskV,
                       float* __restrict__ out_hV)
{
    extern __shared__ char smem_raw[];
    FfnSmem& S = *reinterpret_cast<FfnSmem*>(smem_raw);
    int rb = blockIdx.x;
    int t = threadIdx.x;
    int lane=t&31, warp=t>>5;

    int m = t>>2; int k0 = (t&3)*128;
    const float* src = g_ff + ((size_t)(rb*32+m))*512 + k0;
    #pragma unroll
    for (int i=0;i<32;i++){
        float4 v = *reinterpret_cast<const float4*>(src + i*4);
        S.sA[(k0+i*4+0)*LDT+m]=tf32r(v.x);
        S.sA[(k0+i*4+1)*LDT+m]=tf32r(v.y);
        S.sA[(k0+i*4+2)*LDT+m]=tf32r(v.z);
        S.sA[(k0+i*4+3)*LDT+m]=tf32r(v.w);
    }
    __syncthreads();

    float c[2][4][4];
    mma_core<64,4>(g_Wdoutp, 16, warp*4, S.sA, c, lane);
    __syncthreads();

    int qid=lane>>2, tig=lane&3;
    #pragma unroll
    for (int j=0;j<4;j++){
        int n = (warp*4+j)*8 + tig*2;
        float b0=bdout[n], b1=bdout[n+1];
        #pragma unroll
        for (int mt=0;mt<2;mt++){
            int r = mt*16 + qid;
            size_t node0 = (size_t)(rb*32 + r);
            size_t node1 = node0 + 8;
            S.sA[n*LDT + r]       = c[mt][j][0]+b0 + g_xn[node0*HH + n];
            S.sA[(n+1)*LDT + r]   = c[mt][j][1]+b1 + g_xn[node0*HH + n+1];
            S.sA[n*LDT + r+8]     = c[mt][j][2]+b0 + g_xn[node1*HH + n];
            S.sA[(n+1)*LDT + r+8] = c[mt][j][3]+b1 + g_xn[node1*HH + n+1];
        }
    }
    __syncthreads();

    if (t < 32){
        float s=0.f, q=0.f;
        #pragma unroll 4
        for (int cf=0;cf<HH;cf++){ float v=S.sA[cf*LDT+t]; s+=v; q+=v*v; }
        float mu = s*(1.f/HH);
        S.mu[t]=mu;
        S.rstd[t]=rsqrtf(q*(1.f/HH)-mu*mu+1e-5f);
    }
    __syncthreads();

    float gg=g2[t], bb=be2[t];
    for (int r=0;r<32;r++){
        size_t node = (size_t)(rb*32+r);
        float y = (S.sA[t*LDT+r]-S.mu[r])*S.rstd[r]*gg+bb;
        y *= maskV[node];
        g_hV[node*HH+t]=y;
        out_hV[node*HH+t]=y;
    }
}

// ============================================================
extern "C" void kernel_launch(void* const* d_in, const int* in_sizes, int n_in,
                              void* d_out, int out_size)
{
    const float* hV    =(const float*)d_in[0];
    const float* hE    =(const float*)d_in[1];
    const int*   Eidx  =(const int*)  d_in[2];
    const float* X     =(const float*)d_in[3];
    const float* maskV =(const float*)d_in[4];
    const float* maskA =(const float*)d_in[5];
    const float* Wp_node=(const float*)d_in[6];  const float* bp_node=(const float*)d_in[7];
    const float* Wp_edge=(const float*)d_in[8];  const float* bp_edge=(const float*)d_in[9];
    const float* W1 =(const float*)d_in[10]; const float* b1 =(const float*)d_in[11];
    const float* W2 =(const float*)d_in[12]; const float* b2 =(const float*)d_in[13];
    const float* W3 =(const float*)d_in[14]; const float* b3 =(const float*)d_in[15];
    const float* W11=(const float*)d_in[16]; const float* b11=(const float*)d_in[17];
    const float* W12=(const float*)d_in[18]; const float* b12=(const float*)d_in[19];
    const float* W13=(const float*)d_in[20]; const float* b13=(const float*)d_in[21];
    const float* Wdin =(const float*)d_in[22]; const float* bdin =(const float*)d_in[23];
    const float* Wdout=(const float*)d_in[24]; const float* bdout=(const float*)d_in[25];
    const float* g1=(const float*)d_in[26]; const float* be1=(const float*)d_in[27];
    const float* g2=(const float*)d_in[28]; const float* be2=(const float*)d_in[29];
    const float* g3=(const float*)d_in[30]; const float* be3=(const float*)d_in[31];

    float* out_hV = (float*)d_out;
    float* out_hE = out_hV + (size_t)NB*HH;

    int smem_msg = (int)sizeof(MsgSmem1);
    int smem_ffn = (int)sizeof(FfnSmem);
    cudaFuncSetAttribute(k_node, cudaFuncAttributeMaxDynamicSharedMemorySize, smem_msg);
    cudaFuncSetAttribute(k_edge, cudaFuncAttributeMaxDynamicSharedMemorySize, smem_msg);
    cudaFuncSetAttribute(k_ffn2, cudaFuncAttributeMaxDynamicSharedMemorySize, smem_ffn);

    uint32_t *p1,*p2,*p3,*p11,*p12,*p13;
    float *pdin,*pdout,*phv,*pw1h,*pw11h;
    cudaGetSymbolAddress((void**)&p1,   g_W1pb);
    cudaGetSymbolAddress((void**)&p2,   g_W2pb);
    cudaGetSymbolAddress((void**)&p3,   g_W3pb);
    cudaGetSymbolAddress((void**)&p11,  g_W11pb);
    cudaGetSymbolAddress((void**)&p12,  g_W12pb);
    cudaGetSymbolAddress((void**)&p13,  g_W13pb);
    cudaGetSymbolAddress((void**)&pdin, g_Wdinp);
    cudaGetSymbolAddress((void**)&pdout,g_Wdoutp);
    cudaGetSymbolAddress((void**)&phv,  g_hV);
    cudaGetSymbolAddress((void**)&pw1h, g_W1hp);
    cudaGetSymbolAddress((void**)&pw11h,g_W11hp);

    k_packb<<<dim3(29,16,6),32>>>(W1,W2,W3,W11,W12,W13,p1,p2,p3,p11,p12,p13);
    k_packA<<<dim3(64,4,4),dim3(32,16)>>>(Wdin,Wdout,W1,W11,pdin,pdout,pw1h,pw11h);

    k_prep<<<NB/32,128>>>(hV, Wp_node, bp_node, pw1h, b1, X, 1);
    k_node<<<NB,128,smem_msg>>>(hV,hE,Eidx,maskA,b2,b3,g1,be1);
    k_ffn1<<<dim3(128,4),128>>>(bdin);
    k_ffn2<<<128,128,smem_ffn>>>(bdout,g2,be2,maskV,out_hV);
    k_prep<<<NB/32,128>>>(phv, Wp_edge, bp_edge, pw11h, b11, X, 0);
    k_edge<<<NB,128,smem_msg>>>(hE,Eidx,b12,b13,g3,be3,out_hE);
}

// round 15
// speedup vs baseline: 1.4427x; 1.4427x over previous
#include <cuda_runtime.h>
#include <cuda_bf16.h>
#include <math.h>
#include <stdint.h>

#define BB 2
#define LL 2048
#define KK 32
#define HH 128
#define PP 8
#define MSG 456
#define LDT 40        /* tf32 FFN tiles */
#define NB (BB*LL)    /* 4096 nodes */

#define LDK 344       /* bf16 elems per mi row (688B stride, conflict-free) */
#define LDH 136       /* bf16 elems per h row (272B stride) */
#define LDF 132       /* fp32 msg row */
#define H1_OFF 0      /* bf16 offset of h1 in A0 */
#define H2_OFF 4352   /* bf16 offset of h2 in A0 (byte 8704) */

// -------- scratch --------
__device__ float g_R [NB*9];
__device__ float g_t [NB*3];
__device__ float g_pl[NB*24];
__device__ float g_pg[NB*24];
__device__ float g_hV[NB*HH];
__device__ float g_xn[NB*HH];
__device__ float g_u [NB*HH];
__device__ float g_ff[(size_t)NB*4*HH];

// tf32 packed weights
__device__ float g_Wdinp [16*64*64];
__device__ float g_Wdoutp[64*16*64];
__device__ float g_W1hp  [16*16*64];
__device__ float g_W11hp [16*16*64];

// bf16 packed message weights, dense lane-major:
// element (kc, tile j=g*4+jl with pair h=jl>>1, jp=jl&1, lane, reg r) at
//   [(((kc*8 + g*2 + h)*32 + lane)*4 + jp*2 + r]
// -> per (kc,g): two 16B/lane dense blocks; per-kc uint32 stride = 1024 (unchanged).
__device__ __align__(16) uint32_t g_W1pb [29*16*64];
__device__ __align__(16) uint32_t g_W2pb [ 8*16*64];
__device__ __align__(16) uint32_t g_W3pb [ 8*16*64];
__device__ __align__(16) uint32_t g_W11pb[29*16*64];
__device__ __align__(16) uint32_t g_W12pb[ 8*16*64];
__device__ __align__(16) uint32_t g_W13pb[ 8*16*64];

__device__ __forceinline__ float gelu_f(float x){
    return 0.5f*x*(1.0f+erff(x*0.70710678118654752440f));
}
__device__ __forceinline__ float tf32r(float x){
    uint32_t u; asm("cvt.rna.tf32.f32 %0, %1;" : "=r"(u) : "f"(x));
    return __uint_as_float(u);
}
__device__ __forceinline__ uint32_t bf16x2(float lo, float hi){
    __nv_bfloat162 h = __floats2bfloat162_rn(lo, hi);
    return *reinterpret_cast<uint32_t*>(&h);
}
__device__ __forceinline__ void mma8(float* c, const uint32_t* a, uint32_t b0, uint32_t b1){
    asm volatile("mma.sync.aligned.m16n8k8.row.col.f32.tf32.tf32.f32 "
        "{%0,%1,%2,%3},{%4,%5,%6,%7},{%8,%9},{%0,%1,%2,%3};"
        : "+f"(c[0]),"+f"(c[1]),"+f"(c[2]),"+f"(c[3])
        : "r"(a[0]),"r"(a[1]),"r"(a[2]),"r"(a[3]),"r"(b0),"r"(b1));
}
__device__ __forceinline__ void mma16816(float* c, const uint32_t* a, uint32_t b0, uint32_t b1){
    asm volatile("mma.sync.aligned.m16n8k16.row.col.f32.bf16.bf16.f32 "
        "{%0,%1,%2,%3},{%4,%5,%6,%7},{%8,%9},{%0,%1,%2,%3};"
        : "+f"(c[0]),"+f"(c[1]),"+f"(c[2]),"+f"(c[3])
        : "r"(a[0]),"r"(a[1]),"r"(a[2]),"r"(a[3]),"r"(b0),"r"(b1));
}
__device__ __forceinline__ void ldsm4(uint32_t* r, uint32_t addr){
    asm volatile("ldmatrix.sync.aligned.m8n8.x4.shared.b16 {%0,%1,%2,%3}, [%4];"
        : "=r"(r[0]),"=r"(r[1]),"=r"(r[2]),"=r"(r[3]) : "r"(addr));
}

// ============================================================
// tf32 weight packs merged: z=0 Wdin, z=1 Wdout, z=2 W1 head, z=3 W11 head
// ============================================================
__global__ void k_packA(const float* __restrict__ Wdin, const float* __restrict__ Wdout,
                        const float* __restrict__ W1,  const float* __restrict__ W11,
                        float* pdin, float* pdout, float* pw1h, float* pw11h)
{
    int z = blockIdx.z;
    const float* W; float* out; int N, KC;
    switch(z){
        case 0: W=Wdin;  out=pdin;  N=512; KC=16; break;
        case 1: W=Wdout; out=pdout; N=128; KC=64; break;
        case 2: W=W1;    out=pw1h;  N=128; KC=16; break;
        default:W=W11;   out=pw11h; N=128; KC=16; break;
    }
    int ntiles = N >> 3;
    int kc = blockIdx.x; if (kc >= KC) return;
    int j  = blockIdx.y*16 + threadIdx.y; if (j >= ntiles) return;
    int lane = threadIdx.x;
    int row  = kc*8 + (lane&3);
    int col  = j*8 + (lane>>2);
    float b0 = W[(size_t)row*N + col];
    float b1 = W[(size_t)(row+4)*N + col];
    float* o = out + (((size_t)kc*ntiles + j)*32 + lane)*2;
    o[0] = tf32r(b0); o[1] = tf32r(b1);
}

// ============================================================
// bf16 weight pack (dense lane-major layout). grid(29,16,6) block 32.
// ============================================================
__global__ void k_packb(const float* __restrict__ W1,const float* __restrict__ W2,
                        const float* __restrict__ W3,const float* __restrict__ W11,
                        const float* __restrict__ W12,const float* __restrict__ W13,
                        uint32_t* o1,uint32_t* o2,uint32_t* o3,
                        uint32_t* o11,uint32_t* o12,uint32_t* o13)
{
    int z = blockIdx.z;
    const float* src; uint32_t* dst; int Ktot;
    switch(z){
        case 0: src=W1;  dst=o1;  Ktot=MSG; break;
        case 1: src=W2;  dst=o2;  Ktot=HH;  break;
        case 2: src=W3;  dst=o3;  Ktot=HH;  break;
        case 3: src=W11; dst=o11; Ktot=MSG; break;
        case 4: src=W12; dst=o12; Ktot=HH;  break;
        default:src=W13; dst=o13; Ktot=HH;  break;
    }
    int kc = blockIdx.x;
    if (kc >= (Ktot+15)/16) return;
    int j = blockIdx.y, lane = threadIdx.x;
    int g = j>>2, jl = j&3;
    int h = jl>>1, jp = jl&1;
    int n = j*8 + (lane>>2);
    #pragma unroll
    for (int r=0;r<2;r++){
        int k = kc*16 + (lane&3)*2 + 8*r;
        float v0 = (k   < Ktot)? src[(size_t)k*HH + n]     : 0.f;
        float v1 = (k+1 < Ktot)? src[(size_t)(k+1)*HH + n] : 0.f;
        dst[(((size_t)kc*8 + g*2 + h)*32 + lane)*4 + jp*2 + r] = bf16x2(v0, v1);
    }
}

// ============================================================
// tf32 MMA core (NJ n-tiles per warp)
// ============================================================
template<int NKC, int NJ>
__device__ __forceinline__ void mma_core(const float* __restrict__ Bpack, int ntiles, int jbase,
                                         const float* sA, float c[2][NJ][4], int lane)
{
    int qid = lane>>2, tig = lane&3;
    #pragma unroll
    for (int mt=0;mt<2;mt++)
        #pragma unroll
        for (int j=0;j<NJ;j++)
            #pragma unroll
            for (int i=0;i<4;i++) c[mt][j][i]=0.f;
    const float* bbase = Bpack + (size_t)jbase*64 + lane*2;
    #pragma unroll 4
    for (int kc=0; kc<NKC; kc++){
        const float* a0p = sA + (kc*8+tig)*LDT;
        const float* a1p = a0p + 4*LDT;
        uint32_t a[2][4];
        a[0][0]=__float_as_uint(a0p[qid]);
        a[0][1]=__float_as_uint(a0p[qid+8]);
        a[0][2]=__float_as_uint(a1p[qid]);
        a[0][3]=__float_as_uint(a1p[qid+8]);
        a[1][0]=__float_as_uint(a0p[qid+16]);
        a[1][1]=__float_as_uint(a0p[qid+24]);
        a[1][2]=__float_as_uint(a1p[qid+16]);
        a[1][3]=__float_as_uint(a1p[qid+24]);
        const float* bp = bbase + (size_t)kc*ntiles*64;
        #pragma unroll
        for (int j=0;j<NJ;j++){
            float2 bv = *reinterpret_cast<const float2*>(bp + (size_t)j*64);
            uint32_t b0=__float_as_uint(bv.x), b1=__float_as_uint(bv.y);
            mma8(c[0][j], a[0], b0, b1);
            mma8(c[1][j], a[1], b0, b1);
        }
    }
}

// ============================================================
// Fused per-pass prep: frames (or R reload) + head GEMM -> g_u
// + 24-dim projection -> g_pl + p_global -> g_pg.
// ============================================================
struct PrepSmem {
    float sA[HH*LDT];
    float sW[HH*24];
    float spl[32*24];
    float sR[32*9];
    float st[32*3];
};

__global__ void k_prep(const float* __restrict__ src,
                       const float* __restrict__ Wp,
                       const float* __restrict__ bp,
                       const float* __restrict__ Bpack,
                       const float* __restrict__ biasHead,
                       const float* __restrict__ X,
                       int do_frames)
{
    __shared__ PrepSmem S;
    int rb = blockIdx.x;
    int t = threadIdx.x;
    int lane=t&31, warp=t>>5;

    {
        int m = t>>2; int k0 = (t&3)*32;
        const float* s = src + ((size_t)(rb*32+m))*HH + k0;
        #pragma unroll
        for (int i=0;i<8;i++){
            float4 v = *reinterpret_cast<const float4*>(s + i*4);
            S.sA[(k0+i*4+0)*LDT+m]=tf32r(v.x);
            S.sA[(k0+i*4+1)*LDT+m]=tf32r(v.y);
            S.sA[(k0+i*4+2)*LDT+m]=tf32r(v.z);
            S.sA[(k0+i*4+3)*LDT+m]=tf32r(v.w);
        }
    }
    for (int i=t;i<HH*24;i+=128) S.sW[i] = Wp[i];
    if (do_frames){
        if (t < 32){
            int node = rb*32 + t;
            const float* Xp = X + (size_t)node*12;
            float Nx=Xp[0],Ny=Xp[1],Nz=Xp[2];
            float Ax=Xp[3],Ay=Xp[4],Az=Xp[5];
            float Cx=Xp[6],Cy=Xp[7],Cz=Xp[8];
            float e0x=Ax-Nx, e0y=Ay-Ny, e0z=Az-Nz;
            float inv = 1.0f/sqrtf(e0x*e0x+e0y*e0y+e0z*e0z + 1e-8f);
            e0x*=inv; e0y*=inv; e0z*=inv;
            float e1x=Cx-Ax, e1y=Cy-Ay, e1z=Cz-Az;
            float d = e0x*e1x+e0y*e1y+e0z*e1z;
            e1x-=e0x*d; e1y-=e0y*d; e1z-=e0z*d;
            inv = 1.0f/sqrtf(e1x*e1x+e1y*e1y+e1z*e1z + 1e-8f);
            e1x*=inv; e1y*=inv; e1z*=inv;
            float e2x=e0y*e1z-e0z*e1y;
            float e2y=e0z*e1x-e0x*e1z;
            float e2z=e0x*e1y-e0y*e1x;
            float R0=e0x,R1=e1x,R2=e2x,R3=e0y,R4=e1y,R5=e2y,R6=e0z,R7=e1z,R8=e2z;
            S.sR[t*9+0]=R0; S.sR[t*9+1]=R1; S.sR[t*9+2]=R2;
            S.sR[t*9+3]=R3; S.sR[t*9+4]=R4; S.sR[t*9+5]=R5;
            S.sR[t*9+6]=R6; S.sR[t*9+7]=R7; S.sR[t*9+8]=R8;
            S.st[t*3+0]=Ax; S.st[t*3+1]=Ay; S.st[t*3+2]=Az;
            float* Rg = g_R + node*9;
            Rg[0]=R0; Rg[1]=R1; Rg[2]=R2; Rg[3]=R3; Rg[4]=R4;
            Rg[5]=R5; Rg[6]=R6; Rg[7]=R7; Rg[8]=R8;
            g_t[node*3+0]=Ax; g_t[node*3+1]=Ay; g_t[node*3+2]=Az;
        }
    } else {
        for (int i=t;i<32*9;i+=128) S.sR[i] = g_R[(size_t)rb*32*9 + i];
        for (int i=t;i<32*3;i+=128) S.st[i] = g_t[(size_t)rb*32*3 + i];
    }
    __syncthreads();

    {
        float c[2][4][4];
        mma_core<16,4>(Bpack, 16, warp*4, S.sA, c, lane);
        int qid=lane>>2, tig=lane&3;
        #pragma unroll
        for (int j=0;j<4;j++){
            int n = (warp*4+j)*8 + tig*2;
            float b0=biasHead[n], b1=biasHead[n+1];
            #pragma unroll
            for (int mt=0;mt<2;mt++){
                int r = rb*32 + mt*16 + qid;
                g_u[(size_t)r*HH + n]       = c[mt][j][0]+b0;
                g_u[(size_t)r*HH + n+1]     = c[mt][j][1]+b1;
                g_u[(size_t)(r+8)*HH + n]   = c[mt][j][2]+b0;
                g_u[(size_t)(r+8)*HH + n+1] = c[mt][j][3]+b1;
            }
        }
    }

    #pragma unroll
    for (int i=0;i<6;i++){
        int idx = i*128 + t;
        int m = idx/24, j = idx%24;
        float acc = bp[j];
        #pragma unroll 8
        for (int f=0; f<HH; f++) acc += S.sA[f*LDT+m]*S.sW[f*24+j];
        S.spl[m*24+j] = acc;
        g_pl[((size_t)rb*32+m)*24 + j] = acc;
    }
    __syncthreads();

    #pragma unroll
    for (int i=0;i<6;i++){
        int idx = i*128 + t;
        int m = idx/24, l = idx%24;
        int p = l/3, ii = l%3;
        const float* R = S.sR + m*9;
        const float* pl = S.spl + m*24 + p*3;
        g_pg[((size_t)rb*32+m)*24 + l] =
            S.st[m*3+ii] + R[ii*3+0]*pl[0] + R[ii*3+1]*pl[1] + R[ii*3+2]*pl[2];
    }
}

// ============================================================
// Message-kernel shared memory: ONE node per CTA, A1 eliminated (~23.6KB)
// ============================================================
struct __align__(16) MsgSmem1 {
    __nv_bfloat16 A0[KK*LDK];   // 22016 B
    float hv[HH];
    float uu[HH];
    float Rr[9], tvv[3], pll[24], pgg[24];
    float mask[KK];
    int   nbidx[KK];
    float red[8];
};

// ============================================================
// bf16 MMA core, dense B: 2 x ld.global.v4 per kc, 16B lane stride (dense).
// Rolled kc loop (no unroll) — keeps L0 I$ footprint small.
// ============================================================
template<int NKC>
__device__ __forceinline__ void mma_bf16(const uint32_t* __restrict__ Bp, int nq,
                                         uint32_t aAddr, int ldkB, int lane,
                                         float c[2][4][4])
{
    #pragma unroll
    for (int mt=0;mt<2;mt++)
        #pragma unroll
        for (int j=0;j<4;j++)
            #pragma unroll
            for (int i=0;i<4;i++) c[mt][j][i]=0.f;

    uint32_t arow = aAddr + (uint32_t)((lane&15)*ldkB) + ((lane>>4)&1)*16;
    const uint4* bbase = reinterpret_cast<const uint4*>(Bp) + ((size_t)nq*2*32 + lane);
    for (int kc=0; kc<NKC; kc++){
        uint32_t a[2][4];
        #pragma unroll
        for (int mt=0;mt<2;mt++) ldsm4(a[mt], arow + mt*16*ldkB + kc*32);
        const uint4* bp = bbase + (size_t)kc*256;   // per-kc stride 1024 uint32 = 256 uint4
        uint4 lo = bp[0];      // tiles nq*4+0, nq*4+1
        uint4 hi = bp[32];     // tiles nq*4+2, nq*4+3
        #pragma unroll
        for (int mt=0;mt<2;mt++){
            mma16816(c[mt][0], a[mt], lo.x, lo.y);
            mma16816(c[mt][1], a[mt], lo.z, lo.w);
            mma16816(c[mt][2], a[mt], hi.x, hi.y);
            mma16816(c[mt][3], a[mt], hi.z, hi.w);
        }
    }
}

// epilogues: rows are local [0,32)
__device__ __forceinline__ void epi_gelu_u(float c[2][4][4], const float* __restrict__ uv,
                                           __nv_bfloat16* dst, int lane, int nq)
{
    int qid=lane>>2, tig=lane&3;
    #pragma unroll
    for (int mt=0;mt<2;mt++){
        int r0 = mt*16 + qid;
        #pragma unroll
        for (int j=0;j<4;j++){
            int n0 = nq*32 + j*8 + tig*2;
            float b0=uv[n0], b1=uv[n0+1];
            *reinterpret_cast<uint32_t*>(dst + (size_t)r0*LDH + n0) =
                bf16x2(gelu_f(c[mt][j][0]+b0), gelu_f(c[mt][j][1]+b1));
            *reinterpret_cast<uint32_t*>(dst + (size_t)(r0+8)*LDH + n0) =
                bf16x2(gelu_f(c[mt][j][2]+b0), gelu_f(c[mt][j][3]+b1));
        }
    }
}

__device__ __forceinline__ void epi_gelu_bf16(float c[2][4][4], const float* __restrict__ bias,
                                              __nv_bfloat16* dst, int lane, int nq)
{
    int qid=lane>>2, tig=lane&3;
    #pragma unroll
    for (int mt=0;mt<2;mt++){
        int r0 = mt*16 + qid;
        #pragma unroll
        for (int j=0;j<4;j++){
            int n0 = nq*32 + j*8 + tig*2;
            float b0=bias[n0], b1=bias[n0+1];
            *reinterpret_cast<uint32_t*>(dst + (size_t)r0*LDH + n0) =
                bf16x2(gelu_f(c[mt][j][0]+b0), gelu_f(c[mt][j][1]+b1));
            *reinterpret_cast<uint32_t*>(dst + (size_t)(r0+8)*LDH + n0) =
                bf16x2(gelu_f(c[mt][j][2]+b0), gelu_f(c[mt][j][3]+b1));
        }
    }
}

__device__ __forceinline__ void epi_float(float c[2][4][4], const float* __restrict__ bias,
                                          float* msgF, int lane, int nq)
{
    int qid=lane>>2, tig=lane&3;
    #pragma unroll
    for (int mt=0;mt<2;mt++){
        int r0 = mt*16 + qid;
        #pragma unroll
        for (int j=0;j<4;j++){
            int n0 = nq*32 + j*8 + tig*2;
            float b0=bias[n0], b1=bias[n0+1];
            msgF[(size_t)r0*LDF + n0]       = c[mt][j][0]+b0;
            msgF[(size_t)r0*LDF + n0+1]     = c[mt][j][1]+b1;
            msgF[(size_t)(r0+8)*LDF + n0]   = c[mt][j][2]+b0;
            msgF[(size_t)(r0+8)*LDF + n0+1] = c[mt][j][3]+b1;
        }
    }
}

// Param load. t in [0,128).
__device__ __forceinline__ void load_node_params(MsgSmem1& S, int node, int t,
                                                 const float* __restrict__ hVsrc,
                                                 const int* __restrict__ Eidx,
                                                 const float* __restrict__ maskA)
{
    S.hv[t] = hVsrc[(size_t)node*HH + t];
    S.uu[t] = g_u[(size_t)node*HH + t];
    if (t < KK){
        S.nbidx[t] = Eidx[(size_t)node*KK + t];
        S.mask[t]  = maskA ? maskA[(size_t)node*KK + t] : 1.0f;
    }
    if (t < 9)  S.Rr[t]  = g_R[node*9 + t];
    if (t < 3)  S.tvv[t] = g_t[node*3 + t];
    if (t < 24){ S.pll[t] = g_pl[node*24 + t]; S.pgg[t] = g_pg[node*24 + t]; }
}

// mi build: warp w builds rows w*8..+8; geometry all 128 threads, 2 points each.
__device__ __forceinline__ void build_mi1(MsgSmem1& S, int node, int b, int w,
                                          int lane, int t,
                                          const float* __restrict__ hVsrc,
                                          const float* __restrict__ hE)
{
    #pragma unroll
    for (int i=0;i<8;i++){
        int gr = w*8 + i;
        size_t e = (size_t)node*KK + gr;
        int nb = S.nbidx[gr];
        const float4* he4 = reinterpret_cast<const float4*>(hE + e*HH);
        const float4* nb4 = reinterpret_cast<const float4*>(hVsrc + ((size_t)b*LL + nb)*HH);
        __nv_bfloat16* row = S.A0 + (size_t)gr*LDK;
        float4 x;
        x = he4[lane];
        *reinterpret_cast<uint2*>(row + lane*4)      = make_uint2(bf16x2(x.x,x.y), bf16x2(x.z,x.w));
        x = nb4[lane];
        *reinterpret_cast<uint2*>(row + HH + lane*4) = make_uint2(bf16x2(x.x,x.y), bf16x2(x.z,x.w));
        if (lane < 8) reinterpret_cast<uint32_t*>(row + 328)[lane] = 0u;  // pad 328..343
    }
    {
        int gr = t>>2;
        int p0 = (t&3)*2;
        int nb = S.nbidx[gr];
        const float* npg = g_pg + ((size_t)b*LL + nb)*24;
        __nv_bfloat16* q = S.A0 + (size_t)gr*LDK + 2*HH;
        #pragma unroll
        for (int p=p0;p<p0+2;p++){
            float plx=S.pll[p*3], ply=S.pll[p*3+1], plz=S.pll[p*3+2];
            q[p*3+0]=__float2bfloat16_rn(plx);
            q[p*3+1]=__float2bfloat16_rn(ply);
            q[p*3+2]=__float2bfloat16_rn(plz);
            q[24+p] =__float2bfloat16_rn(sqrtf(plx*plx+ply*ply+plz*plz+1e-8f));
            float dx=npg[p*3+0]-S.tvv[0], dy=npg[p*3+1]-S.tvv[1], dz=npg[p*3+2]-S.tvv[2];
            float nlx = S.Rr[0]*dx + S.Rr[3]*dy + S.Rr[6]*dz;
            float nly = S.Rr[1]*dx + S.Rr[4]*dy + S.Rr[7]*dz;
            float nlz = S.Rr[2]*dx + S.Rr[5]*dy + S.Rr[8]*dz;
            q[32+p*3+0]=__float2bfloat16_rn(nlx);
            q[32+p*3+1]=__float2bfloat16_rn(nly);
            q[32+p*3+2]=__float2bfloat16_rn(nlz);
            q[56+p]=__float2bfloat16_rn(sqrtf(nlx*nlx+nly*nly+nlz*nlz+1e-8f));
            float gx=S.pgg[p*3+0]-npg[p*3+0];
            float gy=S.pgg[p*3+1]-npg[p*3+1];
            float gz=S.pgg[p*3+2]-npg[p*3+2];
            q[64+p]=__float2bfloat16_rn(sqrtf(gx*gx+gy*gy+gz*gz+1e-8f));
        }
    }
}

// Three chained GEMMs, A1-free region reuse inside A0.
__device__ __forceinline__ void run_msg_gemms(MsgSmem1& S,
    const uint32_t* __restrict__ B1,
    const uint32_t* __restrict__ B2, const float* __restrict__ b2,
    const uint32_t* __restrict__ B3, const float* __restrict__ b3,
    int w, int lane)
{
    uint32_t a0 = (uint32_t)__cvta_generic_to_shared(S.A0);
    float* msgF = reinterpret_cast<float*>(S.A0);
    float c[2][4][4];

    // GEMM1 reads mi (full A0). Skip 8 kc blocks (handled via g_u); stride unchanged.
    mma_bf16<21>(B1 + (size_t)8*16*64, w, a0, LDK*2, lane, c);
    __syncthreads();                              // all mi reads done
    epi_gelu_u(c, S.uu, S.A0 + H1_OFF, lane, w);  // h1 -> [0,8704)
    __syncthreads();                              // h1 ready

    // GEMM2 reads h1, writes h2 -> [8704,17408)
    mma_bf16<8>(B2, w, a0 + H1_OFF*2, LDH*2, lane, c);
    epi_gelu_bf16(c, b2, S.A0 + H2_OFF, lane, w);
    __syncthreads();                              // h2 ready

    // GEMM3 reads h2, writes msgF fp32 -> [0,16896) after barrier
    mma_bf16<8>(B3, w, a0 + H2_OFF*2, LDH*2, lane, c);
    __syncthreads();                              // all h2 reads done
    epi_float(c, b3, msgF, lane, w);
    __syncthreads();
}

// ============================================================
// Node message kernel: 1 node/CTA, 128 threads, 8 CTAs/SM
// ============================================================
__global__ __launch_bounds__(128,8) void k_node(
    const float* __restrict__ hV, const float* __restrict__ hE,
    const int* __restrict__ Eidx, const float* __restrict__ maskA,
    const float* __restrict__ b2, const float* __restrict__ b3,
    const float* __restrict__ g1, const float* __restrict__ be1)
{
    extern __shared__ char smem_raw[];
    MsgSmem1& S = *reinterpret_cast<MsgSmem1*>(smem_raw);
    int node = blockIdx.x;
    int b    = node / LL;
    int t    = threadIdx.x;
    int w = t>>5, lane = t&31;

    load_node_params(S, node, t, hV, Eidx, maskA);
    __syncthreads();
    build_mi1(S, node, b, w, lane, t, hV, hE);
    __syncthreads();
    run_msg_gemms(S, g_W1pb, g_W2pb, b2, g_W3pb, b3, w, lane);

    const float* msgF = reinterpret_cast<const float*>(S.A0);
    float acc = 0.f;
    #pragma unroll
    for (int r=0;r<KK;r++) acc += S.mask[r] * msgF[(size_t)r*LDF + t];
    float x = S.hv[t] + acc*(1.0f/KK);
    float s=x, q=x*x;
    #pragma unroll
    for (int o=16;o>0;o>>=1){
        s += __shfl_down_sync(0xffffffffu, s, o);
        q += __shfl_down_sync(0xffffffffu, q, o);
    }
    if (lane==0){ S.red[w]=s; S.red[4+w]=q; }
    __syncthreads();
    float ts = S.red[0]+S.red[1]+S.red[2]+S.red[3];
    float tq = S.red[4]+S.red[5]+S.red[6]+S.red[7];
    float mu = ts*(1.0f/HH);
    float rstd = rsqrtf(tq*(1.0f/HH)-mu*mu+1e-5f);
    g_xn[(size_t)node*HH + t] = (x-mu)*rstd*g1[t] + be1[t];
}

// ============================================================
// Edge message kernel: 1 node/CTA
// ============================================================
__global__ __launch_bounds__(128,8) void k_edge(
    const float* __restrict__ hE, const int* __restrict__ Eidx,
    const float* __restrict__ b2, const float* __restrict__ b3,
    const float* __restrict__ g3, const float* __restrict__ be3,
    float* __restrict__ out_hE)
{
    extern __shared__ char smem_raw[];
    MsgSmem1& S = *reinterpret_cast<MsgSmem1*>(smem_raw);
    int node = blockIdx.x;
    int b    = node / LL;
    int t    = threadIdx.x;
    int w = t>>5, lane = t&31;

    load_node_params(S, node, t, g_hV, Eidx, (const float*)0);
    __syncthreads();
    build_mi1(S, node, b, w, lane, t, g_hV, hE);
    __syncthreads();
    run_msg_gemms(S, g_W11pb, g_W12pb, b2, g_W13pb, b3, w, lane);

    const float* msgF = reinterpret_cast<const float*>(S.A0);
    #pragma unroll
    for (int i=0;i<8;i++){
        int grl = w*8+i;
        size_t e = (size_t)node*KK + grl;
        float4 hv_ = reinterpret_cast<const float4*>(hE + e*HH)[lane];
        float4 mv  = reinterpret_cast<const float4*>(msgF + (size_t)grl*LDF)[lane];
        float x0 = mv.x+hv_.x, x1 = mv.y+hv_.y, x2 = mv.z+hv_.z, x3 = mv.w+hv_.w;
        float s = x0+x1+x2+x3;
        float q = x0*x0+x1*x1+x2*x2+x3*x3;
        #pragma unroll
        for (int o=16;o>0;o>>=1){
            s += __shfl_xor_sync(0xffffffffu, s, o);
            q += __shfl_xor_sync(0xffffffffu, q, o);
        }
        float mu = s*(1.0f/HH);
        float rstd = rsqrtf(q*(1.0f/HH)-mu*mu+1e-5f);
        int f0 = lane*4;
        float4 gg = *reinterpret_cast<const float4*>(g3 + f0);
        float4 bb = *reinterpret_cast<const float4*>(be3 + f0);
        float4 o4;
        o4.x = (x0-mu)*rstd*gg.x + bb.x;
        o4.y = (x1-mu)*rstd*gg.y + bb.y;
        o4.z = (x2-mu)*rstd*gg.z + bb.z;
        o4.w = (x3-mu)*rstd*gg.w + bb.w;
        *reinterpret_cast<float4*>(out_hE + e*HH + f0) = o4;
    }
}

// ============================================================
// tf32 FFN (unchanged)
// ============================================================
__global__ void k_ffn1(const float* __restrict__ bdin)
{
    __shared__ float sA[HH*LDT];
    int rb = blockIdx.x, cb = blockIdx.y;
    int t = threadIdx.x;
    int lane=t&31, warp=t>>5;

    int m = t>>2; int k0 = (t&3)*32;
    const float* src = g_xn + ((size_t)(rb*32+m))*HH + k0;
    #pragma unroll
    for (int i=0;i<8;i++){
        float4 v = *reinterpret_cast<const float4*>(src + i*4);
        sA[(k0+i*4+0)*LDT+m]=tf32r(v.x);
        sA[(k0+i*4+1)*LDT+m]=tf32r(v.y);
        sA[(k0+i*4+2)*LDT+m]=tf32r(v.z);
        sA[(k0+i*4+3)*LDT+m]=tf32r(v.w);
    }
    __syncthreads();

    float c[2][4][4];
    mma_core<16,4>(g_Wdinp, 64, cb*16 + warp*4, sA, c, lane);

    int qid=lane>>2, tig=lane&3;
    #pragma unroll
    for (int j=0;j<4;j++){
        int n = (cb*16+warp*4+j)*8 + tig*2;
        float b0=bdin[n], b1=bdin[n+1];
        #pragma unroll
        for (int mt=0;mt<2;mt++){
            int r = rb*32 + mt*16 + qid;
            g_ff[(size_t)r*512 + n]       = gelu_f(c[mt][j][0]+b0);
            g_ff[(size_t)r*512 + n+1]     = gelu_f(c[mt][j][1]+b1);
            g_ff[(size_t)(r+8)*512 + n]   = gelu_f(c[mt][j][2]+b0);
            g_ff[(size_t)(r+8)*512 + n+1] = gelu_f(c[mt][j][3]+b1);
        }
    }
}

struct FfnSmem {
    float sA[4*HH*LDT];
    float mu[32], rstd[32];
};

__global__ void k_ffn2(const float* __restrict__ bdout,
                       const float* __restrict__ g2, const float* __restrict__ be2,
                       const float* __restrict__ maskV,
                       float* __restrict__ out_hV)
{
    extern __shared__ char smem_raw[];
    FfnSmem& S = *reinterpret_cast<FfnSmem*>(smem_raw);
    int rb = blockIdx.x;
    int t = threadIdx.x;
    int lane=t&31, warp=t>>5;

    int m = t>>2; int k0 = (t&3)*128;
    const float* src = g_ff + ((size_t)(rb*32+m))*512 + k0;
    #pragma unroll
    for (int i=0;i<32;i++){
        float4 v = *reinterpret_cast<const float4*>(src + i*4);
        S.sA[(k0+i*4+0)*LDT+m]=tf32r(v.x);
        S.sA[(k0+i*4+1)*LDT+m]=tf32r(v.y);
        S.sA[(k0+i*4+2)*LDT+m]=tf32r(v.z);
        S.sA[(k0+i*4+3)*LDT+m]=tf32r(v.w);
    }
    __syncthreads();

    float c[2][4][4];
    mma_core<64,4>(g_Wdoutp, 16, warp*4, S.sA, c, lane);
    __syncthreads();

    int qid=lane>>2, tig=lane&3;
    #pragma unroll
    for (int j=0;j<4;j++){
        int n = (warp*4+j)*8 + tig*2;
        float b0=bdout[n], b1=bdout[n+1];
        #pragma unroll
        for (int mt=0;mt<2;mt++){
            int r = mt*16 + qid;
            size_t node0 = (size_t)(rb*32 + r);
            size_t node1 = node0 + 8;
            S.sA[n*LDT + r]       = c[mt][j][0]+b0 + g_xn[node0*HH + n];
            S.sA[(n+1)*LDT + r]   = c[mt][j][1]+b1 + g_xn[node0*HH + n+1];
            S.sA[n*LDT + r+8]     = c[mt][j][2]+b0 + g_xn[node1*HH + n];
            S.sA[(n+1)*LDT + r+8] = c[mt][j][3]+b1 + g_xn[node1*HH + n+1];
        }
    }
    __syncthreads();

    if (t < 32){
        float s=0.f, q=0.f;
        #pragma unroll 4
        for (int cf=0;cf<HH;cf++){ float v=S.sA[cf*LDT+t]; s+=v; q+=v*v; }
        float mu = s*(1.f/HH);
        S.mu[t]=mu;
        S.rstd[t]=rsqrtf(q*(1.f/HH)-mu*mu+1e-5f);
    }
    __syncthreads();

    float gg=g2[t], bb=be2[t];
    for (int r=0;r<32;r++){
        size_t node = (size_t)(rb*32+r);
        float y = (S.sA[t*LDT+r]-S.mu[r])*S.rstd[r]*gg+bb;
        y *= maskV[node];
        g_hV[node*HH+t]=y;
        out_hV[node*HH+t]=y;
    }
}

// ============================================================
extern "C" void kernel_launch(void* const* d_in, const int* in_sizes, int n_in,
                              void* d_out, int out_size)
{
    const float* hV    =(const float*)d_in[0];
    const float* hE    =(const float*)d_in[1];
    const int*   Eidx  =(const int*)  d_in[2];
    const float* X     =(const float*)d_in[3];
    const float* maskV =(const float*)d_in[4];
    const float* maskA =(const float*)d_in[5];
    const float* Wp_node=(const float*)d_in[6];  const float* bp_node=(const float*)d_in[7];
    const float* Wp_edge=(const float*)d_in[8];  const float* bp_edge=(const float*)d_in[9];
    const float* W1 =(const float*)d_in[10]; const float* b1 =(const float*)d_in[11];
    const float* W2 =(const float*)d_in[12]; const float* b2 =(const float*)d_in[13];
    const float* W3 =(const float*)d_in[14]; const float* b3 =(const float*)d_in[15];
    const float* W11=(const float*)d_in[16]; const float* b11=(const float*)d_in[17];
    const float* W12=(const float*)d_in[18]; const float* b12=(const float*)d_in[19];
    const float* W13=(const float*)d_in[20]; const float* b13=(const float*)d_in[21];
    const float* Wdin =(const float*)d_in[22]; const float* bdin =(const float*)d_in[23];
    const float* Wdout=(const float*)d_in[24]; const float* bdout=(const float*)d_in[25];
    const float* g1=(const float*)d_in[26]; const float* be1=(const float*)d_in[27];
    const float* g2=(const float*)d_in[28]; const float* be2=(const float*)d_in[29];
    const float* g3=(const float*)d_in[30]; const float* be3=(const float*)d_in[31];

    float* out_hV = (float*)d_out;
    float* out_hE = out_hV + (size_t)NB*HH;

    int smem_msg = (int)sizeof(MsgSmem1);
    int smem_ffn = (int)sizeof(FfnSmem);
    cudaFuncSetAttribute(k_node, cudaFuncAttributeMaxDynamicSharedMemorySize, smem_msg);
    cudaFuncSetAttribute(k_edge, cudaFuncAttributeMaxDynamicSharedMemorySize, smem_msg);
    cudaFuncSetAttribute(k_ffn2, cudaFuncAttributeMaxDynamicSharedMemorySize, smem_ffn);

    uint32_t *p1,*p2,*p3,*p11,*p12,*p13;
    float *pdin,*pdout,*phv,*pw1h,*pw11h;
    cudaGetSymbolAddress((void**)&p1,   g_W1pb);
    cudaGetSymbolAddress((void**)&p2,   g_W2pb);
    cudaGetSymbolAddress((void**)&p3,   g_W3pb);
    cudaGetSymbolAddress((void**)&p11,  g_W11pb);
    cudaGetSymbolAddress((void**)&p12,  g_W12pb);
    cudaGetSymbolAddress((void**)&p13,  g_W13pb);
    cudaGetSymbolAddress((void**)&pdin, g_Wdinp);
    cudaGetSymbolAddress((void**)&pdout,g_Wdoutp);
    cudaGetSymbolAddress((void**)&phv,  g_hV);
    cudaGetSymbolAddress((void**)&pw1h, g_W1hp);
    cudaGetSymbolAddress((void**)&pw11h,g_W11hp);

    k_packb<<<dim3(29,16,6),32>>>(W1,W2,W3,W11,W12,W13,p1,p2,p3,p11,p12,p13);
    k_packA<<<dim3(64,4,4),dim3(32,16)>>>(Wdin,Wdout,W1,W11,pdin,pdout,pw1h,pw11h);

    k_prep<<<NB/32,128>>>(hV, Wp_node, bp_node, pw1h, b1, X, 1);
    k_node<<<NB,128,smem_msg>>>(hV,hE,Eidx,maskA,b2,b3,g1,be1);
    k_ffn1<<<dim3(128,4),128>>>(bdin);
    k_ffn2<<<128,128,smem_ffn>>>(bdout,g2,be2,maskV,out_hV);
    k_prep<<<NB/32,128>>>(phv, Wp_edge, bp_edge, pw11h, b11, X, 0);
    k_edge<<<NB,128,smem_msg>>>(hE,Eidx,b12,b13,g3,be3,out_hE);
}

// round 17
// speedup vs baseline: 1.5620x; 1.0827x over previous
#include <cuda_runtime.h>
#include <cuda_bf16.h>
#include <math.h>
#include <stdint.h>

#define BB 2
#define LL 2048
#define KK 32
#define HH 128
#define PP 8
#define MSG 456
#define LDT 40        /* tf32 FFN tiles */
#define NB (BB*LL)    /* 4096 nodes */

#define LDK 216       /* bf16 elems per mi row: hE[0..128) + geom[128..200) + pad[200..216) */
                      /* 432B stride: ldsm phase offsets r*27 mod 8 = permutation -> conflict-free */
#define NKC1 13       /* GEMM1 kc blocks (208 cols) */
#define LDH 136       /* bf16 elems per h row (272B stride) */
#define LDF 132       /* fp32 msg row */
#define A0SZ 8704     /* bf16 elems in A0 = 17408B >= max(mi 13824B, h2 end 17408B, msgF 16896B) */
#define H1_OFF 0      /* bf16 offset of h1 in A0 */
#define H2_OFF 4352   /* bf16 offset of h2 in A0 (byte 8704) */

// -------- scratch --------
__device__ float g_R [NB*9];
__device__ float g_t [NB*3];
__device__ float g_pl[NB*24];
__device__ float g_pg[NB*24];
__device__ float g_hV[NB*HH];
__device__ float g_xn[NB*HH];
__device__ float g_u [NB*HH];    /* per-node W1[0:128] head (bias incl.) */
__device__ float g_v [NB*HH];    /* per-node W1[256:384] (nb_hV) contribution */
__device__ float g_ff[(size_t)NB*4*HH];

// tf32 packed weights
__device__ float g_Wdinp [16*64*64];
__device__ float g_Wdoutp[64*16*64];
__device__ float g_W1hp  [16*16*64];
__device__ float g_W11hp [16*16*64];
__device__ float g_W1vp  [16*16*64];
__device__ float g_W11vp [16*16*64];

// bf16 packed message weights, dense lane-major (R15 layout):
// element (kb, tile j=g*4+jl, h=jl>>1, jp=jl&1, lane, r) at
//   [(((kb*8 + g*2 + h)*32 + lane)*4 + jp*2 + r]
// W1/W11: kb 0..12 maps to original kc {8..15, 24..28} (head + nb blocks hoisted out).
__device__ __align__(16) uint32_t g_W1pb [NKC1*16*64];
__device__ __align__(16) uint32_t g_W2pb [ 8*16*64];
__device__ __align__(16) uint32_t g_W3pb [ 8*16*64];
__device__ __align__(16) uint32_t g_W11pb[NKC1*16*64];
__device__ __align__(16) uint32_t g_W12pb[ 8*16*64];
__device__ __align__(16) uint32_t g_W13pb[ 8*16*64];

__device__ __forceinline__ float gelu_f(float x){
    return 0.5f*x*(1.0f+erff(x*0.70710678118654752440f));
}
__device__ __forceinline__ float tf32r(float x){
    uint32_t u; asm("cvt.rna.tf32.f32 %0, %1;" : "=r"(u) : "f"(x));
    return __uint_as_float(u);
}
__device__ __forceinline__ uint32_t bf16x2(float lo, float hi){
    __nv_bfloat162 h = __floats2bfloat162_rn(lo, hi);
    return *reinterpret_cast<uint32_t*>(&h);
}
__device__ __forceinline__ void mma8(float* c, const uint32_t* a, uint32_t b0, uint32_t b1){
    asm volatile("mma.sync.aligned.m16n8k8.row.col.f32.tf32.tf32.f32 "
        "{%0,%1,%2,%3},{%4,%5,%6,%7},{%8,%9},{%0,%1,%2,%3};"
        : "+f"(c[0]),"+f"(c[1]),"+f"(c[2]),"+f"(c[3])
        : "r"(a[0]),"r"(a[1]),"r"(a[2]),"r"(a[3]),"r"(b0),"r"(b1));
}
__device__ __forceinline__ void mma16816(float* c, const uint32_t* a, uint32_t b0, uint32_t b1){
    asm volatile("mma.sync.aligned.m16n8k16.row.col.f32.bf16.bf16.f32 "
        "{%0,%1,%2,%3},{%4,%5,%6,%7},{%8,%9},{%0,%1,%2,%3};"
        : "+f"(c[0]),"+f"(c[1]),"+f"(c[2]),"+f"(c[3])
        : "r"(a[0]),"r"(a[1]),"r"(a[2]),"r"(a[3]),"r"(b0),"r"(b1));
}
__device__ __forceinline__ void ldsm4(uint32_t* r, uint32_t addr){
    asm volatile("ldmatrix.sync.aligned.m8n8.x4.shared.b16 {%0,%1,%2,%3}, [%4];"
        : "=r"(r[0]),"=r"(r[1]),"=r"(r[2]),"=r"(r[3]) : "r"(addr));
}

// ============================================================
// tf32 weight packs: z=0 Wdin, z=1 Wdout, z=2/3 W1/W11 head, z=4/5 W1/W11 nb-slice
// ============================================================
__global__ void k_packA(const float* __restrict__ Wdin, const float* __restrict__ Wdout,
                        const float* __restrict__ W1,  const float* __restrict__ W11,
                        float* pdin, float* pdout, float* pw1h, float* pw11h,
                        float* pw1v, float* pw11v)
{
    int z = blockIdx.z;
    const float* W; float* out; int N, KC;
    switch(z){
        case 0: W=Wdin;           out=pdin;  N=512; KC=16; break;
        case 1: W=Wdout;          out=pdout; N=128; KC=64; break;
        case 2: W=W1;             out=pw1h;  N=128; KC=16; break;
        case 3: W=W11;            out=pw11h; N=128; KC=16; break;
        case 4: W=W1 +(size_t)256*HH; out=pw1v;  N=128; KC=16; break;
        default:W=W11+(size_t)256*HH; out=pw11v; N=128; KC=16; break;
    }
    int ntiles = N >> 3;
    int kc = blockIdx.x; if (kc >= KC) return;
    int j  = blockIdx.y*16 + threadIdx.y; if (j >= ntiles) return;
    int lane = threadIdx.x;
    int row  = kc*8 + (lane&3);
    int col  = j*8 + (lane>>2);
    float b0 = W[(size_t)row*N + col];
    float b1 = W[(size_t)(row+4)*N + col];
    float* o = out + (((size_t)kc*ntiles + j)*32 + lane)*2;
    o[0] = tf32r(b0); o[1] = tf32r(b1);
}

// ============================================================
// bf16 weight pack (dense lane-major). grid(13,16,6) block 32.
// z=0/3 (W1/W11): block kb maps to src kc {8..15, 24..28}.
// z=1,2,4,5 (W2,W3,W12,W13): identity, 8 blocks.
// ============================================================
__global__ void k_packb(const float* __restrict__ W1,const float* __restrict__ W2,
                        const float* __restrict__ W3,const float* __restrict__ W11,
                        const float* __restrict__ W12,const float* __restrict__ W13,
                        uint32_t* o1,uint32_t* o2,uint32_t* o3,
                        uint32_t* o11,uint32_t* o12,uint32_t* o13)
{
    int z = blockIdx.z;
    const float* src; uint32_t* dst; int Ktot; int nblocks;
    switch(z){
        case 0: src=W1;  dst=o1;  Ktot=MSG; nblocks=NKC1; break;
        case 1: src=W2;  dst=o2;  Ktot=HH;  nblocks=8;    break;
        case 2: src=W3;  dst=o3;  Ktot=HH;  nblocks=8;    break;
        case 3: src=W11; dst=o11; Ktot=MSG; nblocks=NKC1; break;
        case 4: src=W12; dst=o12; Ktot=HH;  nblocks=8;    break;
        default:src=W13; dst=o13; Ktot=HH;  nblocks=8;    break;
    }
    int kb = blockIdx.x;
    if (kb >= nblocks) return;
    int kcsrc = kb;
    if (z==0 || z==3) kcsrc = (kb < 8) ? (8 + kb) : (24 + (kb - 8));
    int j = blockIdx.y, lane = threadIdx.x;
    int g = j>>2, jl = j&3;
    int h = jl>>1, jp = jl&1;
    int n = j*8 + (lane>>2);
    #pragma unroll
    for (int r=0;r<2;r++){
        int k = kcsrc*16 + (lane&3)*2 + 8*r;
        float v0 = (k   < Ktot)? src[(size_t)k*HH + n]     : 0.f;
        float v1 = (k+1 < Ktot)? src[(size_t)(k+1)*HH + n] : 0.f;
        dst[(((size_t)kb*8 + g*2 + h)*32 + lane)*4 + jp*2 + r] = bf16x2(v0, v1);
    }
}

// ============================================================
// tf32 MMA core (NJ n-tiles per warp)
// ============================================================
template<int NKC, int NJ>
__device__ __forceinline__ void mma_core(const float* __restrict__ Bpack, int ntiles, int jbase,
                                         const float* sA, float c[2][NJ][4], int lane)
{
    int qid = lane>>2, tig = lane&3;
    #pragma unroll
    for (int mt=0;mt<2;mt++)
        #pragma unroll
        for (int j=0;j<NJ;j++)
            #pragma unroll
            for (int i=0;i<4;i++) c[mt][j][i]=0.f;
    const float* bbase = Bpack + (size_t)jbase*64 + lane*2;
    #pragma unroll 4
    for (int kc=0; kc<NKC; kc++){
        const float* a0p = sA + (kc*8+tig)*LDT;
        const float* a1p = a0p + 4*LDT;
        uint32_t a[2][4];
        a[0][0]=__float_as_uint(a0p[qid]);
        a[0][1]=__float_as_uint(a0p[qid+8]);
        a[0][2]=__float_as_uint(a1p[qid]);
        a[0][3]=__float_as_uint(a1p[qid+8]);
        a[1][0]=__float_as_uint(a0p[qid+16]);
        a[1][1]=__float_as_uint(a0p[qid+24]);
        a[1][2]=__float_as_uint(a1p[qid+16]);
        a[1][3]=__float_as_uint(a1p[qid+24]);
        const float* bp = bbase + (size_t)kc*ntiles*64;
        #pragma unroll
        for (int j=0;j<NJ;j++){
            float2 bv = *reinterpret_cast<const float2*>(bp + (size_t)j*64);
            uint32_t b0=__float_as_uint(bv.x), b1=__float_as_uint(bv.y);
            mma8(c[0][j], a[0], b0, b1);
            mma8(c[1][j], a[1], b0, b1);
        }
    }
}

// ============================================================
// Fused per-pass prep: frames (or R reload) + head GEMM -> g_u
// + nb-slice GEMM -> g_v + 24-dim projection -> g_pl + p_global -> g_pg.
// ============================================================
struct PrepSmem {
    float sA[HH*LDT];
    float sW[HH*24];
    float spl[32*24];
    float sR[32*9];
    float st[32*3];
};

__global__ void k_prep(const float* __restrict__ src,
                       const float* __restrict__ Wp,
                       const float* __restrict__ bp,
                       const float* __restrict__ Bpack,
                       const float* __restrict__ biasHead,
                       const float* __restrict__ BpackV,
                       const float* __restrict__ X,
                       int do_frames)
{
    __shared__ PrepSmem S;
    int rb = blockIdx.x;
    int t = threadIdx.x;
    int lane=t&31, warp=t>>5;

    {
        int m = t>>2; int k0 = (t&3)*32;
        const float* s = src + ((size_t)(rb*32+m))*HH + k0;
        #pragma unroll
        for (int i=0;i<8;i++){
            float4 v = *reinterpret_cast<const float4*>(s + i*4);
            S.sA[(k0+i*4+0)*LDT+m]=tf32r(v.x);
            S.sA[(k0+i*4+1)*LDT+m]=tf32r(v.y);
            S.sA[(k0+i*4+2)*LDT+m]=tf32r(v.z);
            S.sA[(k0+i*4+3)*LDT+m]=tf32r(v.w);
        }
    }
    for (int i=t;i<HH*24;i+=128) S.sW[i] = Wp[i];
    if (do_frames){
        if (t < 32){
            int node = rb*32 + t;
            const float* Xp = X + (size_t)node*12;
            float Nx=Xp[0],Ny=Xp[1],Nz=Xp[2];
            float Ax=Xp[3],Ay=Xp[4],Az=Xp[5];
            float Cx=Xp[6],Cy=Xp[7],Cz=Xp[8];
            float e0x=Ax-Nx, e0y=Ay-Ny, e0z=Az-Nz;
            float inv = 1.0f/sqrtf(e0x*e0x+e0y*e0y+e0z*e0z + 1e-8f);
            e0x*=inv; e0y*=inv; e0z*=inv;
            float e1x=Cx-Ax, e1y=Cy-Ay, e1z=Cz-Az;
            float d = e0x*e1x+e0y*e1y+e0z*e1z;
            e1x-=e0x*d; e1y-=e0y*d; e1z-=e0z*d;
            inv = 1.0f/sqrtf(e1x*e1x+e1y*e1y+e1z*e1z + 1e-8f);
            e1x*=inv; e1y*=inv; e1z*=inv;
            float e2x=e0y*e1z-e0z*e1y;
            float e2y=e0z*e1x-e0x*e1z;
            float e2z=e0x*e1y-e0y*e1x;
            float R0=e0x,R1=e1x,R2=e2x,R3=e0y,R4=e1y,R5=e2y,R6=e0z,R7=e1z,R8=e2z;
            S.sR[t*9+0]=R0; S.sR[t*9+1]=R1; S.sR[t*9+2]=R2;
            S.sR[t*9+3]=R3; S.sR[t*9+4]=R4; S.sR[t*9+5]=R5;
            S.sR[t*9+6]=R6; S.sR[t*9+7]=R7; S.sR[t*9+8]=R8;
            S.st[t*3+0]=Ax; S.st[t*3+1]=Ay; S.st[t*3+2]=Az;
            float* Rg = g_R + node*9;
            Rg[0]=R0; Rg[1]=R1; Rg[2]=R2; Rg[3]=R3; Rg[4]=R4;
            Rg[5]=R5; Rg[6]=R6; Rg[7]=R7; Rg[8]=R8;
            g_t[node*3+0]=Ax; g_t[node*3+1]=Ay; g_t[node*3+2]=Az;
        }
    } else {
        for (int i=t;i<32*9;i+=128) S.sR[i] = g_R[(size_t)rb*32*9 + i];
        for (int i=t;i<32*3;i+=128) S.st[i] = g_t[(size_t)rb*32*3 + i];
    }
    __syncthreads();

    // head GEMM -> g_u (bias included)
    {
        float c[2][4][4];
        mma_core<16,4>(Bpack, 16, warp*4, S.sA, c, lane);
        int qid=lane>>2, tig=lane&3;
        #pragma unroll
        for (int j=0;j<4;j++){
            int n = (warp*4+j)*8 + tig*2;
            float b0=biasHead[n], b1=biasHead[n+1];
            #pragma unroll
            for (int mt=0;mt<2;mt++){
                int r = rb*32 + mt*16 + qid;
                g_u[(size_t)r*HH + n]       = c[mt][j][0]+b0;
                g_u[(size_t)r*HH + n+1]     = c[mt][j][1]+b1;
                g_u[(size_t)(r+8)*HH + n]   = c[mt][j][2]+b0;
                g_u[(size_t)(r+8)*HH + n+1] = c[mt][j][3]+b1;
            }
        }
    }
    // nb-slice GEMM -> g_v (no bias)
    {
        float c[2][4][4];
        mma_core<16,4>(BpackV, 16, warp*4, S.sA, c, lane);
        int qid=lane>>2, tig=lane&3;
        #pragma unroll
        for (int j=0;j<4;j++){
            int n = (warp*4+j)*8 + tig*2;
            #pragma unroll
            for (int mt=0;mt<2;mt++){
                int r = rb*32 + mt*16 + qid;
                g_v[(size_t)r*HH + n]       = c[mt][j][0];
                g_v[(size_t)r*HH + n+1]     = c[mt][j][1];
                g_v[(size_t)(r+8)*HH + n]   = c[mt][j][2];
                g_v[(size_t)(r+8)*HH + n+1] = c[mt][j][3];
            }
        }
    }

    #pragma unroll
    for (int i=0;i<6;i++){
        int idx = i*128 + t;
        int m = idx/24, j = idx%24;
        float acc = bp[j];
        #pragma unroll 8
        for (int f=0; f<HH; f++) acc += S.sA[f*LDT+m]*S.sW[f*24+j];
        S.spl[m*24+j] = acc;
        g_pl[((size_t)rb*32+m)*24 + j] = acc;
    }
    __syncthreads();

    #pragma unroll
    for (int i=0;i<6;i++){
        int idx = i*128 + t;
        int m = idx/24, l = idx%24;
        int p = l/3, ii = l%3;
        const float* R = S.sR + m*9;
        const float* pl = S.spl + m*24 + p*3;
        g_pg[((size_t)rb*32+m)*24 + l] =
            S.st[m*3+ii] + R[ii*3+0]*pl[0] + R[ii*3+1]*pl[1] + R[ii*3+2]*pl[2];
    }
}

// ============================================================
// Message-kernel shared memory: ONE node per CTA (~19.5KB)
// A0: mi[32][216] (13824B) -> h1 @0, h2 @8704B -> msgF fp32 @0
// ============================================================
struct __align__(16) MsgSmem1 {
    __nv_bfloat16 A0[A0SZ];   // 17408 B
    float hv[HH];
    float uu[HH];
    float Rr[9], tvv[3], pll[24], pgg[24];
    float mask[KK];
    int   nbidx[KK];
    float red[8];
};

// ============================================================
// bf16 MMA core, dense B: 2 x ld.global.v4 per kc, rolled loop.
// ============================================================
template<int NKC>
__device__ __forceinline__ void mma_bf16(const uint32_t* __restrict__ Bp, int nq,
                                         uint32_t aAddr, int ldkB, int lane,
                                         float c[2][4][4])
{
    #pragma unroll
    for (int mt=0;mt<2;mt++)
        #pragma unroll
        for (int j=0;j<4;j++)
            #pragma unroll
            for (int i=0;i<4;i++) c[mt][j][i]=0.f;

    uint32_t arow = aAddr + (uint32_t)((lane&15)*ldkB) + ((lane>>4)&1)*16;
    const uint4* bbase = reinterpret_cast<const uint4*>(Bp) + ((size_t)nq*2*32 + lane);
    for (int kc=0; kc<NKC; kc++){
        uint32_t a[2][4];
        #pragma unroll
        for (int mt=0;mt<2;mt++) ldsm4(a[mt], arow + mt*16*ldkB + kc*32);
        const uint4* bp = bbase + (size_t)kc*256;
        uint4 lo = bp[0];
        uint4 hi = bp[32];
        #pragma unroll
        for (int mt=0;mt<2;mt++){
            mma16816(c[mt][0], a[mt], lo.x, lo.y);
            mma16816(c[mt][1], a[mt], lo.z, lo.w);
            mma16816(c[mt][2], a[mt], hi.x, hi.y);
            mma16816(c[mt][3], a[mt], hi.z, hi.w);
        }
    }
}

// GEMM1 epilogue: h1 = gelu(c + u[n] + v[nb_row][n])
__device__ __forceinline__ void epi_gelu_uv(float c[2][4][4], const float* __restrict__ uv,
                                            const int* __restrict__ nbidx,
                                            __nv_bfloat16* dst, int lane, int nq)
{
    int qid=lane>>2, tig=lane&3;
    #pragma unroll
    for (int mt=0;mt<2;mt++){
        int r0 = mt*16 + qid;
        const float* v0 = g_v + (size_t)nbidx[r0]*HH;
        const float* v1 = g_v + (size_t)nbidx[r0+8]*HH;
        #pragma unroll
        for (int j=0;j<4;j++){
            int n0 = nq*32 + j*8 + tig*2;
            float b0=uv[n0], b1=uv[n0+1];
            float2 a0 = *reinterpret_cast<const float2*>(v0 + n0);
            float2 a1 = *reinterpret_cast<const float2*>(v1 + n0);
            *reinterpret_cast<uint32_t*>(dst + (size_t)r0*LDH + n0) =
                bf16x2(gelu_f(c[mt][j][0]+b0+a0.x), gelu_f(c[mt][j][1]+b1+a0.y));
            *reinterpret_cast<uint32_t*>(dst + (size_t)(r0+8)*LDH + n0) =
                bf16x2(gelu_f(c[mt][j][2]+b0+a1.x), gelu_f(c[mt][j][3]+b1+a1.y));
        }
    }
}

__device__ __forceinline__ void epi_gelu_bf16(float c[2][4][4], const float* __restrict__ bias,
                                              __nv_bfloat16* dst, int lane, int nq)
{
    int qid=lane>>2, tig=lane&3;
    #pragma unroll
    for (int mt=0;mt<2;mt++){
        int r0 = mt*16 + qid;
        #pragma unroll
        for (int j=0;j<4;j++){
            int n0 = nq*32 + j*8 + tig*2;
            float b0=bias[n0], b1=bias[n0+1];
            *reinterpret_cast<uint32_t*>(dst + (size_t)r0*LDH + n0) =
                bf16x2(gelu_f(c[mt][j][0]+b0), gelu_f(c[mt][j][1]+b1));
            *reinterpret_cast<uint32_t*>(dst + (size_t)(r0+8)*LDH + n0) =
                bf16x2(gelu_f(c[mt][j][2]+b0), gelu_f(c[mt][j][3]+b1));
        }
    }
}

__device__ __forceinline__ void epi_float(float c[2][4][4], const float* __restrict__ bias,
                                          float* msgF, int lane, int nq)
{
    int qid=lane>>2, tig=lane&3;
    #pragma unroll
    for (int mt=0;mt<2;mt++){
        int r0 = mt*16 + qid;
        #pragma unroll
        for (int j=0;j<4;j++){
            int n0 = nq*32 + j*8 + tig*2;
            float b0=bias[n0], b1=bias[n0+1];
            msgF[(size_t)r0*LDF + n0]       = c[mt][j][0]+b0;
            msgF[(size_t)r0*LDF + n0+1]     = c[mt][j][1]+b1;
            msgF[(size_t)(r0+8)*LDF + n0]   = c[mt][j][2]+b0;
            msgF[(size_t)(r0+8)*LDF + n0+1] = c[mt][j][3]+b1;
        }
    }
}

// Param load. t in [0,128).
__device__ __forceinline__ void load_node_params(MsgSmem1& S, int node, int t,
                                                 const float* __restrict__ hVsrc,
                                                 const int* __restrict__ Eidx,
                                                 const float* __restrict__ maskA)
{
    S.hv[t] = hVsrc[(size_t)node*HH + t];
    S.uu[t] = g_u[(size_t)node*HH + t];
    if (t < KK){
        S.nbidx[t] = Eidx[(size_t)node*KK + t];
        S.mask[t]  = maskA ? maskA[(size_t)node*KK + t] : 1.0f;
    }
    if (t < 9)  S.Rr[t]  = g_R[node*9 + t];
    if (t < 3)  S.tvv[t] = g_t[node*3 + t];
    if (t < 24){ S.pll[t] = g_pl[node*24 + t]; S.pgg[t] = g_pg[node*24 + t]; }
}

// mi build: hE at cols 0..127, geometry at 128..199, pad 200..215.
// nbidx converted to batch-global in caller NOT needed: nbidx stored raw; gather adds b*LL.
__device__ __forceinline__ void build_mi1(MsgSmem1& S, int node, int b, int w,
                                          int lane, int t,
                                          const float* __restrict__ hE)
{
    #pragma unroll
    for (int i=0;i<8;i++){
        int gr = w*8 + i;
        size_t e = (size_t)node*KK + gr;
        const float4* he4 = reinterpret_cast<const float4*>(hE + e*HH);
        __nv_bfloat16* row = S.A0 + (size_t)gr*LDK;
        float4 x = he4[lane];
        *reinterpret_cast<uint2*>(row + lane*4) = make_uint2(bf16x2(x.x,x.y), bf16x2(x.z,x.w));
        if (lane < 8) reinterpret_cast<uint32_t*>(row)[100+lane] = 0u;  // pad cols 200..215
    }
    {
        int gr = t>>2;
        int p0 = (t&3)*2;
        int nb = S.nbidx[gr];
        const float* npg = g_pg + ((size_t)b*LL + nb)*24;
        __nv_bfloat16* q = S.A0 + (size_t)gr*LDK + HH;   // geometry base = col 128
        #pragma unroll
        for (int p=p0;p<p0+2;p++){
            float plx=S.pll[p*3], ply=S.pll[p*3+1], plz=S.pll[p*3+2];
            q[p*3+0]=__float2bfloat16_rn(plx);
            q[p*3+1]=__float2bfloat16_rn(ply);
            q[p*3+2]=__float2bfloat16_rn(plz);
            q[24+p] =__float2bfloat16_rn(sqrtf(plx*plx+ply*ply+plz*plz+1e-8f));
            float dx=npg[p*3+0]-S.tvv[0], dy=npg[p*3+1]-S.tvv[1], dz=npg[p*3+2]-S.tvv[2];
            float nlx = S.Rr[0]*dx + S.Rr[3]*dy + S.Rr[6]*dz;
            float nly = S.Rr[1]*dx + S.Rr[4]*dy + S.Rr[7]*dz;
            float nlz = S.Rr[2]*dx + S.Rr[5]*dy + S.Rr[8]*dz;
            q[32+p*3+0]=__float2bfloat16_rn(nlx);
            q[32+p*3+1]=__float2bfloat16_rn(nly);
            q[32+p*3+2]=__float2bfloat16_rn(nlz);
            q[56+p]=__float2bfloat16_rn(sqrtf(nlx*nlx+nly*nly+nlz*nlz+1e-8f));
            float gx=S.pgg[p*3+0]-npg[p*3+0];
            float gy=S.pgg[p*3+1]-npg[p*3+1];
            float gz=S.pgg[p*3+2]-npg[p*3+2];
            q[64+p]=__float2bfloat16_rn(sqrtf(gx*gx+gy*gy+gz*gz+1e-8f));
        }
    }
}

// Three chained GEMMs. nbg = batch-global neighbor indices in smem.
__device__ __forceinline__ void run_msg_gemms(MsgSmem1& S, int b,
    const uint32_t* __restrict__ B1,
    const uint32_t* __restrict__ B2, const float* __restrict__ b2,
    const uint32_t* __restrict__ B3, const float* __restrict__ b3,
    int w, int lane)
{
    uint32_t a0 = (uint32_t)__cvta_generic_to_shared(S.A0);
    float* msgF = reinterpret_cast<float*>(S.A0);
    float c[2][4][4];

    // GEMM1 over mi cols 0..207 (13 kc, W1 kc {8..15,24..28})
    mma_bf16<NKC1>(B1, w, a0, LDK*2, lane, c);
    __syncthreads();                              // all mi reads done
    // epilogue adds u[node] + v[nb_row] (gather). nbidx raw -> global offset b*LL.
    {
        int qid=lane>>2, tig=lane&3;
        #pragma unroll
        for (int mt=0;mt<2;mt++){
            int r0 = mt*16 + qid;
            const float* v0 = g_v + ((size_t)b*LL + S.nbidx[r0])*HH;
            const float* v1 = g_v + ((size_t)b*LL + S.nbidx[r0+8])*HH;
            #pragma unroll
            for (int j=0;j<4;j++){
                int n0 = w*32 + j*8 + tig*2;
                float b0=S.uu[n0], b1=S.uu[n0+1];
                float2 a0v = *reinterpret_cast<const float2*>(v0 + n0);
                float2 a1v = *reinterpret_cast<const float2*>(v1 + n0);
                *reinterpret_cast<uint32_t*>(S.A0 + H1_OFF + (size_t)r0*LDH + n0) =
                    bf16x2(gelu_f(c[mt][j][0]+b0+a0v.x), gelu_f(c[mt][j][1]+b1+a0v.y));
                *reinterpret_cast<uint32_t*>(S.A0 + H1_OFF + (size_t)(r0+8)*LDH + n0) =
                    bf16x2(gelu_f(c[mt][j][2]+b0+a1v.x), gelu_f(c[mt][j][3]+b1+a1v.y));
            }
        }
    }
    __syncthreads();                              // h1 ready

    mma_bf16<8>(B2, w, a0 + H1_OFF*2, LDH*2, lane, c);
    epi_gelu_bf16(c, b2, S.A0 + H2_OFF, lane, w);
    __syncthreads();                              // h2 ready

    mma_bf16<8>(B3, w, a0 + H2_OFF*2, LDH*2, lane, c);
    __syncthreads();                              // all h2 reads done
    epi_float(c, b3, msgF, lane, w);
    __syncthreads();
}

// ============================================================
// Node message kernel: 1 node/CTA, 128 threads, 8 CTAs/SM
// ============================================================
__global__ __launch_bounds__(128,8) void k_node(
    const float* __restrict__ hV, const float* __restrict__ hE,
    const int* __restrict__ Eidx, const float* __restrict__ maskA,
    const float* __restrict__ b2, const float* __restrict__ b3,
    const float* __restrict__ g1, const float* __restrict__ be1)
{
    extern __shared__ char smem_raw[];
    MsgSmem1& S = *reinterpret_cast<MsgSmem1*>(smem_raw);
    int node = blockIdx.x;
    int b    = node / LL;
    int t    = threadIdx.x;
    int w = t>>5, lane = t&31;

    load_node_params(S, node, t, hV, Eidx, maskA);
    __syncthreads();
    build_mi1(S, node, b, w, lane, t, hE);
    __syncthreads();
    run_msg_gemms(S, b, g_W1pb, g_W2pb, b2, g_W3pb, b3, w, lane);

    const float* msgF = reinterpret_cast<const float*>(S.A0);
    float acc = 0.f;
    #pragma unroll
    for (int r=0;r<KK;r++) acc += S.mask[r] * msgF[(size_t)r*LDF + t];
    float x = S.hv[t] + acc*(1.0f/KK);
    float s=x, q=x*x;
    #pragma unroll
    for (int o=16;o>0;o>>=1){
        s += __shfl_down_sync(0xffffffffu, s, o);
        q += __shfl_down_sync(0xffffffffu, q, o);
    }
    if (lane==0){ S.red[w]=s; S.red[4+w]=q; }
    __syncthreads();
    float ts = S.red[0]+S.red[1]+S.red[2]+S.red[3];
    float tq = S.red[4]+S.red[5]+S.red[6]+S.red[7];
    float mu = ts*(1.0f/HH);
    float rstd = rsqrtf(tq*(1.0f/HH)-mu*mu+1e-5f);
    g_xn[(size_t)node*HH + t] = (x-mu)*rstd*g1[t] + be1[t];
}

// ============================================================
// Edge message kernel: 1 node/CTA
// ============================================================
__global__ __launch_bounds__(128,8) void k_edge(
    const float* __restrict__ hE, const int* __restrict__ Eidx,
    const float* __restrict__ b2, const float* __restrict__ b3,
    const float* __restrict__ g3, const float* __restrict__ be3,
    float* __restrict__ out_hE)
{
    extern __shared__ char smem_raw[];
    MsgSmem1& S = *reinterpret_cast<MsgSmem1*>(smem_raw);
    int node = blockIdx.x;
    int b    = node / LL;
    int t    = threadIdx.x;
    int w = t>>5, lane = t&31;

    load_node_params(S, node, t, g_hV, Eidx, (const float*)0);
    __syncthreads();
    build_mi1(S, node, b, w, lane, t, hE);
    __syncthreads();
    run_msg_gemms(S, b, g_W11pb, g_W12pb, b2, g_W13pb, b3, w, lane);

    const float* msgF = reinterpret_cast<const float*>(S.A0);
    #pragma unroll
    for (int i=0;i<8;i++){
        int grl = w*8+i;
        size_t e = (size_t)node*KK + grl;
        float4 hv_ = reinterpret_cast<const float4*>(hE + e*HH)[lane];
        float4 mv  = reinterpret_cast<const float4*>(msgF + (size_t)grl*LDF)[lane];
        float x0 = mv.x+hv_.x, x1 = mv.y+hv_.y, x2 = mv.z+hv_.z, x3 = mv.w+hv_.w;
        float s = x0+x1+x2+x3;
        float q = x0*x0+x1*x1+x2*x2+x3*x3;
        #pragma unroll
        for (int o=16;o>0;o>>=1){
            s += __shfl_xor_sync(0xffffffffu, s, o);
            q += __shfl_xor_sync(0xffffffffu, q, o);
        }
        float mu = s*(1.0f/HH);
        float rstd = rsqrtf(q*(1.0f/HH)-mu*mu+1e-5f);
        int f0 = lane*4;
        float4 gg = *reinterpret_cast<const float4*>(g3 + f0);
        float4 bb = *reinterpret_cast<const float4*>(be3 + f0);
        float4 o4;
        o4.x = (x0-mu)*rstd*gg.x + bb.x;
        o4.y = (x1-mu)*rstd*gg.y + bb.y;
        o4.z = (x2-mu)*rstd*gg.z + bb.z;
        o4.w = (x3-mu)*rstd*gg.w + bb.w;
        *reinterpret_cast<float4*>(out_hE + e*HH + f0) = o4;
    }
}

// ============================================================
// tf32 FFN (unchanged)
// ============================================================
__global__ void k_ffn1(const float* __restrict__ bdin)
{
    __shared__ float sA[HH*LDT];
    int rb = blockIdx.x, cb = blockIdx.y;
    int t = threadIdx.x;
    int lane=t&31, warp=t>>5;

    int m = t>>2; int k0 = (t&3)*32;
    const float* src = g_xn + ((size_t)(rb*32+m))*HH + k0;
    #pragma unroll
    for (int i=0;i<8;i++){
        float4 v = *reinterpret_cast<const float4*>(src + i*4);
        sA[(k0+i*4+0)*LDT+m]=tf32r(v.x);
        sA[(k0+i*4+1)*LDT+m]=tf32r(v.y);
        sA[(k0+i*4+2)*LDT+m]=tf32r(v.z);
        sA[(k0+i*4+3)*LDT+m]=tf32r(v.w);
    }
    __syncthreads();

    float c[2][4][4];
    mma_core<16,4>(g_Wdinp, 64, cb*16 + warp*4, sA, c, lane);

    int qid=lane>>2, tig=lane&3;
    #pragma unroll
    for (int j=0;j<4;j++){
        int n = (cb*16+warp*4+j)*8 + tig*2;
        float b0=bdin[n], b1=bdin[n+1];
        #pragma unroll
        for (int mt=0;mt<2;mt++){
            int r = rb*32 + mt*16 + qid;
            g_ff[(size_t)r*512 + n]       = gelu_f(c[mt][j][0]+b0);
            g_ff[(size_t)r*512 + n+1]     = gelu_f(c[mt][j][1]+b1);
            g_ff[(size_t)(r+8)*512 + n]   = gelu_f(c[mt][j][2]+b0);
            g_ff[(size_t)(r+8)*512 + n+1] = gelu_f(c[mt][j][3]+b1);
        }
    }
}

struct FfnSmem {
    float sA[4*HH*LDT];
    float mu[32], rstd[32];
};

__global__ void k_ffn2(const float* __restrict__ bdout,
                       const float* __restrict__ g2, const float* __restrict__ be2,
                       const float* __restrict__ maskV,
                       float* __restrict__ out_hV)
{
    extern __shared__ char smem_raw[];
    FfnSmem& S = *reinterpret_cast<FfnSmem*>(smem_raw);
    int rb = blockIdx.x;
    int t = threadIdx.x;
    int lane=t&31, warp=t>>5;

    int m = t>>2; int k0 = (t&3)*128;
    const float* src = g_ff + ((size_t)(rb*32+m))*512 + k0;
    #pragma unroll
    for (int i=0;i<32;i++){
        float4 v = *reinterpret_cast<const float4*>(src + i*4);
        S.sA[(k0+i*4+0)*LDT+m]=tf32r(v.x);
        S.sA[(k0+i*4+1)*LDT+m]=tf32r(v.y);
        S.sA[(k0+i*4+2)*LDT+m]=tf32r(v.z);
        S.sA[(k0+i*4+3)*LDT+m]=tf32r(v.w);
    }
    __syncthreads();

    float c[2][4][4];
    mma_core<64,4>(g_Wdoutp, 16, warp*4, S.sA, c, lane);
    __syncthreads();

    int qid=lane>>2, tig=lane&3;
    #pragma unroll
    for (int j=0;j<4;j++){
        int n = (warp*4+j)*8 + tig*2;
        float b0=bdout[n], b1=bdout[n+1];
        #pragma unroll
        for (int mt=0;mt<2;mt++){
            int r = mt*16 + qid;
            size_t node0 = (size_t)(rb*32 + r);
            size_t node1 = node0 + 8;
            S.sA[n*LDT + r]       = c[mt][j][0]+b0 + g_xn[node0*HH + n];
            S.sA[(n+1)*LDT + r]   = c[mt][j][1]+b1 + g_xn[node0*HH + n+1];
            S.sA[n*LDT + r+8]     = c[mt][j][2]+b0 + g_xn[node1*HH + n];
            S.sA[(n+1)*LDT + r+8] = c[mt][j][3]+b1 + g_xn[node1*HH + n+1];
        }
    }
    __syncthreads();

    if (t < 32){
        float s=0.f, q=0.f;
        #pragma unroll 4
        for (int cf=0;cf<HH;cf++){ float v=S.sA[cf*LDT+t]; s+=v; q+=v*v; }
        float mu = s*(1.f/HH);
        S.mu[t]=mu;
        S.rstd[t]=rsqrtf(q*(1.f/HH)-mu*mu+1e-5f);
    }
    __syncthreads();

    float gg=g2[t], bb=be2[t];
    for (int r=0;r<32;r++){
        size_t node = (size_t)(rb*32+r);
        float y = (S.sA[t*LDT+r]-S.mu[r])*S.rstd[r]*gg+bb;
        y *= maskV[node];
        g_hV[node*HH+t]=y;
        out_hV[node*HH+t]=y;
    }
}

// ============================================================
extern "C" void kernel_launch(void* const* d_in, const int* in_sizes, int n_in,
                              void* d_out, int out_size)
{
    const float* hV    =(const float*)d_in[0];
    const float* hE    =(const float*)d_in[1];
    const int*   Eidx  =(const int*)  d_in[2];
    const float* X     =(const float*)d_in[3];
    const float* maskV =(const float*)d_in[4];
    const float* maskA =(const float*)d_in[5];
    const float* Wp_node=(const float*)d_in[6];  const float* bp_node=(const float*)d_in[7];
    const float* Wp_edge=(const float*)d_in[8];  const float* bp_edge=(const float*)d_in[9];
    const float* W1 =(const float*)d_in[10]; const float* b1 =(const float*)d_in[11];
    const float* W2 =(const float*)d_in[12]; const float* b2 =(const float*)d_in[13];
    const float* W3 =(const float*)d_in[14]; const float* b3 =(const float*)d_in[15];
    const float* W11=(const float*)d_in[16]; const float* b11=(const float*)d_in[17];
    const float* W12=(const float*)d_in[18]; const float* b12=(const float*)d_in[19];
    const float* W13=(const float*)d_in[20]; const float* b13=(const float*)d_in[21];
    const float* Wdin =(const float*)d_in[22]; const float* bdin =(const float*)d_in[23];
    const float* Wdout=(const float*)d_in[24]; const float* bdout=(const float*)d_in[25];
    const float* g1=(const float*)d_in[26]; const float* be1=(const float*)d_in[27];
    const float* g2=(const float*)d_in[28]; const float* be2=(const float*)d_in[29];
    const float* g3=(const float*)d_in[30]; const float* be3=(const float*)d_in[31];

    float* out_hV = (float*)d_out;
    float* out_hE = out_hV + (size_t)NB*HH;

    int smem_msg = (int)sizeof(MsgSmem1);
    int smem_ffn = (int)sizeof(FfnSmem);
    cudaFuncSetAttribute(k_node, cudaFuncAttributeMaxDynamicSharedMemorySize, smem_msg);
    cudaFuncSetAttribute(k_edge, cudaFuncAttributeMaxDynamicSharedMemorySize, smem_msg);
    cudaFuncSetAttribute(k_ffn2, cudaFuncAttributeMaxDynamicSharedMemorySize, smem_ffn);

    uint32_t *p1,*p2,*p3,*p11,*p12,*p13;
    float *pdin,*pdout,*phv,*pw1h,*pw11h,*pw1v,*pw11v;
    cudaGetSymbolAddress((void**)&p1,   g_W1pb);
    cudaGetSymbolAddress((void**)&p2,   g_W2pb);
    cudaGetSymbolAddress((void**)&p3,   g_W3pb);
    cudaGetSymbolAddress((void**)&p11,  g_W11pb);
    cudaGetSymbolAddress((void**)&p12,  g_W12pb);
    cudaGetSymbolAddress((void**)&p13,  g_W13pb);
    cudaGetSymbolAddress((void**)&pdin, g_Wdinp);
    cudaGetSymbolAddress((void**)&pdout,g_Wdoutp);
    cudaGetSymbolAddress((void**)&phv,  g_hV);
    cudaGetSymbolAddress((void**)&pw1h, g_W1hp);
    cudaGetSymbolAddress((void**)&pw11h,g_W11hp);
    cudaGetSymbolAddress((void**)&pw1v, g_W1vp);
    cudaGetSymbolAddress((void**)&pw11v,g_W11vp);

    k_packb<<<dim3(NKC1,16,6),32>>>(W1,W2,W3,W11,W12,W13,p1,p2,p3,p11,p12,p13);
    k_packA<<<dim3(64,4,6),dim3(32,16)>>>(Wdin,Wdout,W1,W11,pdin,pdout,pw1h,pw11h,pw1v,pw11v);

    k_prep<<<NB/32,128>>>(hV, Wp_node, bp_node, pw1h, b1, pw1v, X, 1);
    k_node<<<NB,128,smem_msg>>>(hV,hE,Eidx,maskA,b2,b3,g1,be1);
    k_ffn1<<<dim3(128,4),128>>>(bdin);
    k_ffn2<<<128,128,smem_ffn>>>(bdout,g2,be2,maskV,out_hV);
    k_prep<<<NB/32,128>>>(phv, Wp_edge, bp_edge, pw11h, b11, pw11v, X, 0);
    k_edge<<<NB,128,smem_msg>>>(hE,Eidx,b12,b13,g3,be3,out_hE);
}